// round 3
// baseline (speedup 1.0000x reference)
#include <cuda_runtime.h>
#include <cstdint>

// Shapes (fixed):
//  x1  [2,64,8,8,8,8]   x2 [2,32,16,16,16,16]
//  up_w[64,32,2,2,2,2]  up_b[32]
//  w1  [32,64,3,3,3,3]  b1[32]
//  w2  [32,32,3,3,3,3]  b2[32]
//  w3  [32,64]          b3[32]
//  out [2,32,16,16,16,16] fp32

__device__ float g_x1u[2 * 32 * 65536];  // upsampled half of concat
__device__ float g_y1 [2 * 32 * 65536];  // relu(conv1) output

__device__ __forceinline__ unsigned long long pack2(float a, float b) {
    unsigned long long r;
    asm("mov.b64 %0, {%1, %2};" : "=l"(r) : "f"(a), "f"(b));
    return r;
}
__device__ __forceinline__ void unpack2(unsigned long long v, float &a, float &b) {
    asm("mov.b64 {%0, %1}, %2;" : "=f"(a), "=f"(b) : "l"(v));
}
// Packed dual FMA: d.lo += a.lo*b.lo ; d.hi += a.hi*b.hi  (sm_100+)
__device__ __forceinline__ void fma2(unsigned long long &d, unsigned long long a, unsigned long long b) {
    asm("fma.rn.f32x2 %0, %1, %2, %0;" : "+l"(d) : "l"(a), "l"(b));
}
// 4-byte cp.async with runtime src-size (0 => zero-fill)
__device__ __forceinline__ void cpa4(uint32_t saddr, const void* g, int sz) {
    asm volatile("cp.async.ca.shared.global [%0], [%1], 4, %2;"
                 :: "r"(saddr), "l"(g), "r"(sz) : "memory");
}
#define CP_COMMIT() asm volatile("cp.async.commit_group;" ::: "memory")
#define CP_WAIT1()  asm volatile("cp.async.wait_group 1;" ::: "memory")

// ---------------------------------------------------------------------------
// Transposed conv k=2 s=2: x1 [2,64,8^4] -> g_x1u [2,32,16^4]
// ---------------------------------------------------------------------------
__global__ __launch_bounds__(256) void upconv_kernel(
    const float* __restrict__ x1, const float* __restrict__ uw,
    const float* __restrict__ ub)
{
    int bx = blockIdx.x;
    int b = bx >> 9, t = (bx >> 6) & 7, d = (bx >> 3) & 7, h = bx & 7;
    int tid = threadIdx.x;
    int co = tid >> 3, w = tid & 7;

    float acc[16];
    float bias = ub[co];
#pragma unroll
    for (int a = 0; a < 16; a++) acc[a] = bias;

    const float* xp = x1 + (((size_t)b * 64) << 12) + (t << 9) + (d << 6) + (h << 3) + w;
#pragma unroll 4
    for (int ci = 0; ci < 64; ci++) {
        float xv = xp[(size_t)ci << 12];
        const float4* wp = (const float4*)(uw + (((size_t)ci * 32 + co) << 4));
#pragma unroll
        for (int q = 0; q < 4; q++) {
            float4 wv = wp[q];
            acc[q * 4 + 0] += xv * wv.x;
            acc[q * 4 + 1] += xv * wv.y;
            acc[q * 4 + 2] += xv * wv.z;
            acc[q * 4 + 3] += xv * wv.w;
        }
    }
    float* op = g_x1u + (((size_t)(b * 32 + co)) << 16);
#pragma unroll
    for (int a = 0; a < 16; a++) {
        int p = (a >> 3) & 1, q = (a >> 2) & 1, r = (a >> 1) & 1, s = a & 1;
        op[((2 * t + p) << 12) + ((2 * d + q) << 8) + ((2 * h + r) << 4) + (2 * w + s)] = acc[a];
    }
}

// ---------------------------------------------------------------------------
// 4D conv, kernel 3^4, pad 1, Cout=32. One block per (b,t,d); 128 threads,
// each handling TWO (h,w) positions: (h,w) and (h+8,w), 32 Cout as 16 f32x2.
// Double-buffered cp.async pipeline over stages = (valid tt, valid dd, ci-chunk).
// Channels come from two 32-ch halves (concat never materialized).
// SKIP: fused 1x1 conv (w3,b3) over the 64-ch concat + final relu.
// ---------------------------------------------------------------------------
template <int CIN, bool SKIP>
__global__ __launch_bounds__(128, 4) void conv_kernel(
    const float* __restrict__ src0, const float* __restrict__ src1,
    const float* __restrict__ wgt,  const float* __restrict__ bias,
    const float* __restrict__ sk0,  const float* __restrict__ sk1,
    const float* __restrict__ w3,   const float* __restrict__ b3,
    float* __restrict__ out)
{
    constexpr int CI  = 8;            // ci chunk per stage
    constexpr int NCH = CIN / CI;
    constexpr int XS  = CI * 324;     // 2592 floats (18x18 halo per ci)
    constexpr int WS  = CI * 9 * 32;  // 2304 floats ([ci][kh][kw][co])
    constexpr int BUF = XS + WS;      // 4896 floats per buffer

    __shared__ __align__(16) float S[2 * BUF];
    uint32_t sbase = (uint32_t)__cvta_generic_to_shared(S);

    int b = blockIdx.y;
    int t = blockIdx.x >> 4, d = blockIdx.x & 15;
    int tid = threadIdx.x;
    int h = tid >> 4;        // 0..7  (second position is h+8)
    int w = tid & 15;

    int t0 = max(t - 1, 0), nt = min(t + 1, 15) - t0 + 1;
    int d0 = max(d - 1, 0), nd = min(d + 1, 15) - d0 + 1;
    int NST = nt * nd * NCH;

    unsigned long long accA[16], accB[16];
#pragma unroll
    for (int j = 0; j < 16; j++) {
        float v0 = bias[2 * j], v1 = bias[2 * j + 1];
        if constexpr (SKIP) { v0 += b3[2 * j]; v1 += b3[2 * j + 1]; }
        accA[j] = pack2(v0, v1);
        accB[j] = accA[j];
    }

    // ---- stage prefetch: issue cp.asyncs for stage s into buffer bufi ----
    auto prefetch = [&](int s, int bufi) {
        int ch = s % NCH;
        int pr = s / NCH;
        int dd = d0 + pr % nd;
        int tt = t0 + pr / nd;
        int kt = tt - t + 1, kd = dd - d + 1;
        uint32_t xb = sbase + (uint32_t)(bufi * BUF) * 4u;
        uint32_t wb = xb + XS * 4u;
        // X: CI channels of 18x18 haloed plane (zero-fill via src-size 0)
        for (int idx = tid; idx < XS; idx += 128) {
            int ci = idx / 324;
            int rr = idx - ci * 324;
            int r = rr / 18, c2 = rr - r * 18;
            int hh = r - 1, ww = c2 - 1;
            int c = ch * CI + ci;
            const float* sp = (CIN == 64 && c >= 32)
                ? (src1 + (((size_t)(b * 32 + (c - 32))) << 16))
                : (src0 + (((size_t)(b * 32 + (c & 31))) << 16));
            bool ok = ((unsigned)hh < 16u) & ((unsigned)ww < 16u);
            const float* gp = ok ? (sp + ((tt << 12) + (dd << 8) + (hh << 4) + ww)) : sp;
            cpa4(xb + (uint32_t)idx * 4u, gp, ok ? 4 : 0);
        }
        // W: reorder co-innermost for broadcast LDS.128 in compute
        for (int idx = tid; idx < WS; idx += 128) {
            int co = idx & 31;
            int r = idx >> 5;
            int kw = r % 3;
            int kh = (r / 3) % 3;
            int ci = r / 9;
            int c = ch * CI + ci;
            cpa4(wb + (uint32_t)idx * 4u,
                 wgt + ((size_t)co * CIN + c) * 81 + kt * 27 + kd * 9 + kh * 3 + kw, 4);
        }
    };

    // ---- pipeline: prefetch(s+1) overlaps compute(s) ----
    prefetch(0, 0);
    CP_COMMIT();

#pragma unroll 1
    for (int s = 0; s < NST; s++) {
        __syncthreads();                 // buffer (s+1)&1 free (compute s-1 done)
        if (s + 1 < NST) prefetch(s + 1, (s + 1) & 1);
        CP_COMMIT();                     // always commit (possibly empty group)
        CP_WAIT1();                      // stage s deposits (this thread) done
        __syncthreads();                 // all threads' deposits visible

        const float* Xs = S + (s & 1) * BUF;
        const float* Ws = Xs + XS;
#pragma unroll 1
        for (int ci = 0; ci < CI; ci++) {
            const float* xb = Xs + ci * 324 + h * 18 + w;
            const float* wb = Ws + ci * 9 * 32;
#pragma unroll
            for (int kh = 0; kh < 3; kh++) {
#pragma unroll
                for (int kw = 0; kw < 3; kw++) {
                    float xv0 = xb[kh * 18 + kw];
                    float xv1 = xb[kh * 18 + kw + 144];   // (h+8) row
                    unsigned long long xx0 = pack2(xv0, xv0);
                    unsigned long long xx1 = pack2(xv1, xv1);
                    const ulonglong2* wp = (const ulonglong2*)(wb + (kh * 3 + kw) * 32);
#pragma unroll
                    for (int q = 0; q < 8; q++) {
                        ulonglong2 wv = wp[q];
                        fma2(accA[2 * q],     xx0, wv.x);
                        fma2(accA[2 * q + 1], xx0, wv.y);
                        fma2(accB[2 * q],     xx1, wv.x);
                        fma2(accB[2 * q + 1], xx1, wv.y);
                    }
                }
            }
        }
    }

    int pos = (h << 4) + w;      // second position = pos + 128

    if constexpr (SKIP) {
        // Fused 1x1 conv over the 64-channel concat (reuses S)
#pragma unroll 1
        for (int ch = 0; ch < 4; ch++) {
            __syncthreads();
            for (int idx = tid; idx < 16 * 256; idx += 128) {
                int ci = idx >> 8, p = idx & 255;
                int c = ch * 16 + ci;
                const float* sp = (c < 32)
                    ? (sk0 + (((size_t)(b * 32 + c)) << 16))
                    : (sk1 + (((size_t)(b * 32 + c - 32)) << 16));
                S[idx] = sp[(t << 12) + (d << 8) + p];
            }
            for (int idx = tid; idx < 512; idx += 128) {
                int ci = idx >> 5, co = idx & 31;
                S[16 * 256 + idx] = w3[co * 64 + ch * 16 + ci];
            }
            __syncthreads();
#pragma unroll 1
            for (int ci = 0; ci < 16; ci++) {
                float xv0 = S[(ci << 8) + pos];
                float xv1 = S[(ci << 8) + pos + 128];
                unsigned long long xx0 = pack2(xv0, xv0);
                unsigned long long xx1 = pack2(xv1, xv1);
                const ulonglong2* wp = (const ulonglong2*)(S + 16 * 256 + (ci << 5));
#pragma unroll
                for (int q = 0; q < 8; q++) {
                    ulonglong2 wv = wp[q];
                    fma2(accA[2 * q],     xx0, wv.x);
                    fma2(accA[2 * q + 1], xx0, wv.y);
                    fma2(accB[2 * q],     xx1, wv.x);
                    fma2(accB[2 * q + 1], xx1, wv.y);
                }
            }
        }
    }

    size_t obase = ((size_t)b * 32) << 16;
    int opos = (t << 12) + (d << 8) + pos;
#pragma unroll
    for (int j = 0; j < 16; j++) {
        float a0, a1, c0, c1;
        unpack2(accA[j], a0, a1);
        unpack2(accB[j], c0, c1);
        a0 = fmaxf(a0, 0.f); a1 = fmaxf(a1, 0.f);
        c0 = fmaxf(c0, 0.f); c1 = fmaxf(c1, 0.f);
        size_t o0 = obase + (((size_t)(2 * j)) << 16) + opos;
        size_t o1 = obase + (((size_t)(2 * j + 1)) << 16) + opos;
        out[o0]       = a0;
        out[o1]       = a1;
        out[o0 + 128] = c0;   // (h+8) position
        out[o1 + 128] = c1;
    }
}

extern "C" void kernel_launch(void* const* d_in, const int* in_sizes, int n_in,
                              void* d_out, int out_size)
{
    const float* x1   = (const float*)d_in[0];
    const float* x2   = (const float*)d_in[1];
    const float* up_w = (const float*)d_in[2];
    const float* up_b = (const float*)d_in[3];
    const float* w1   = (const float*)d_in[4];
    const float* b1   = (const float*)d_in[5];
    const float* w2   = (const float*)d_in[6];
    const float* b2   = (const float*)d_in[7];
    const float* w3   = (const float*)d_in[8];
    const float* b3   = (const float*)d_in[9];
    float* out = (float*)d_out;

    float *px1u = nullptr, *py1 = nullptr;
    cudaGetSymbolAddress((void**)&px1u, g_x1u);
    cudaGetSymbolAddress((void**)&py1,  g_y1);

    // 1) upsample x1 -> g_x1u (second half of channel concat)
    upconv_kernel<<<1024, 256>>>(x1, up_w, up_b);

    // 2) Y1 = relu(conv4d(concat, w1, b1, pad=1)) -> g_y1
    conv_kernel<64, false><<<dim3(256, 2), 128>>>(
        x2, px1u, w1, b1, nullptr, nullptr, nullptr, nullptr, py1);

    // 3) out = relu(conv4d(Y1, w2, b2, pad=1) + conv1x1(concat, w3, b3))
    conv_kernel<32, true><<<dim3(256, 2), 128>>>(
        py1, nullptr, w2, b2, x2, px1u, w3, b3, out);
}

// round 4
// speedup vs baseline: 1.0033x; 1.0033x over previous
#include <cuda_runtime.h>
#include <cstdint>

// Shapes (fixed):
//  x1  [2,64,8,8,8,8]   x2 [2,32,16,16,16,16]
//  up_w[64,32,2,2,2,2]  up_b[32]
//  w1  [32,64,3,3,3,3]  b1[32]
//  w2  [32,32,3,3,3,3]  b2[32]
//  w3  [32,64]          b3[32]
//  out [2,32,16,16,16,16] fp32

__device__ float g_x1u[2 * 32 * 65536];  // upsampled half of concat
__device__ float g_y1 [2 * 32 * 65536];  // relu(conv1) output

__device__ __forceinline__ unsigned long long pack2(float a, float b) {
    unsigned long long r;
    asm("mov.b64 %0, {%1, %2};" : "=l"(r) : "f"(a), "f"(b));
    return r;
}
__device__ __forceinline__ void unpack2(unsigned long long v, float &a, float &b) {
    asm("mov.b64 {%0, %1}, %2;" : "=f"(a), "=f"(b) : "l"(v));
}
// Packed dual FMA: d.lo += a.lo*b.lo ; d.hi += a.hi*b.hi  (sm_100+)
__device__ __forceinline__ void fma2(unsigned long long &d, unsigned long long a, unsigned long long b) {
    asm("fma.rn.f32x2 %0, %1, %2, %0;" : "+l"(d) : "l"(a), "l"(b));
}
// 4-byte cp.async with runtime src-size (0 => zero-fill)
__device__ __forceinline__ void cpa4(uint32_t saddr, const void* g, int sz) {
    asm volatile("cp.async.ca.shared.global [%0], [%1], 4, %2;"
                 :: "r"(saddr), "l"(g), "r"(sz) : "memory");
}
#define CP_COMMIT() asm volatile("cp.async.commit_group;" ::: "memory")
#define CP_WAIT1()  asm volatile("cp.async.wait_group 1;" ::: "memory")

// ---------------------------------------------------------------------------
// Transposed conv k=2 s=2: x1 [2,64,8^4] -> g_x1u [2,32,16^4]
// ---------------------------------------------------------------------------
__global__ __launch_bounds__(256) void upconv_kernel(
    const float* __restrict__ x1, const float* __restrict__ uw,
    const float* __restrict__ ub)
{
    int bx = blockIdx.x;
    int b = bx >> 9, t = (bx >> 6) & 7, d = (bx >> 3) & 7, h = bx & 7;
    int tid = threadIdx.x;
    int co = tid >> 3, w = tid & 7;

    float acc[16];
    float bias = ub[co];
#pragma unroll
    for (int a = 0; a < 16; a++) acc[a] = bias;

    const float* xp = x1 + (((size_t)b * 64) << 12) + (t << 9) + (d << 6) + (h << 3) + w;
#pragma unroll 4
    for (int ci = 0; ci < 64; ci++) {
        float xv = xp[(size_t)ci << 12];
        const float4* wp = (const float4*)(uw + (((size_t)ci * 32 + co) << 4));
#pragma unroll
        for (int q = 0; q < 4; q++) {
            float4 wv = wp[q];
            acc[q * 4 + 0] += xv * wv.x;
            acc[q * 4 + 1] += xv * wv.y;
            acc[q * 4 + 2] += xv * wv.z;
            acc[q * 4 + 3] += xv * wv.w;
        }
    }
    float* op = g_x1u + (((size_t)(b * 32 + co)) << 16);
#pragma unroll
    for (int a = 0; a < 16; a++) {
        int p = (a >> 3) & 1, q = (a >> 2) & 1, r = (a >> 1) & 1, s = a & 1;
        op[((2 * t + p) << 12) + ((2 * d + q) << 8) + ((2 * h + r) << 4) + (2 * w + s)] = acc[a];
    }
}

// ---------------------------------------------------------------------------
// 4D conv, kernel 3^4, pad 1, Cout=32. One block per (b,t,d); 128 threads,
// each handling TWO (h,w) positions: (h,w) and (h+8,w), 32 Cout as 16 f32x2.
// Double-buffered cp.async pipeline over stages = (valid tt, valid dd, ci-chunk).
// Channels come from two 32-ch halves (concat never materialized).
// SKIP: fused 1x1 conv (w3,b3) over the 64-ch concat + final relu.
// ---------------------------------------------------------------------------
template <int CIN, bool SKIP>
__global__ __launch_bounds__(128, 4) void conv_kernel(
    const float* __restrict__ src0, const float* __restrict__ src1,
    const float* __restrict__ wgt,  const float* __restrict__ bias,
    const float* __restrict__ sk0,  const float* __restrict__ sk1,
    const float* __restrict__ w3,   const float* __restrict__ b3,
    float* __restrict__ out)
{
    constexpr int CI  = 8;            // ci chunk per stage
    constexpr int NCH = CIN / CI;
    constexpr int XS  = CI * 324;     // 2592 floats (18x18 halo per ci)
    constexpr int WS  = CI * 9 * 32;  // 2304 floats ([ci][kh][kw][co])
    constexpr int BUF = XS + WS;      // 4896 floats per buffer

    __shared__ __align__(16) float S[2 * BUF];
    uint32_t sbase = (uint32_t)__cvta_generic_to_shared(S);

    int b = blockIdx.y;
    int t = blockIdx.x >> 4, d = blockIdx.x & 15;
    int tid = threadIdx.x;
    int h = tid >> 4;        // 0..7  (second position is h+8)
    int w = tid & 15;

    int t0 = max(t - 1, 0), nt = min(t + 1, 15) - t0 + 1;
    int d0 = max(d - 1, 0), nd = min(d + 1, 15) - d0 + 1;
    int NST = nt * nd * NCH;

    unsigned long long accA[16], accB[16];
#pragma unroll
    for (int j = 0; j < 16; j++) {
        float v0 = bias[2 * j], v1 = bias[2 * j + 1];
        if constexpr (SKIP) { v0 += b3[2 * j]; v1 += b3[2 * j + 1]; }
        accA[j] = pack2(v0, v1);
        accB[j] = accA[j];
    }

    // ---- stage prefetch: issue cp.asyncs for stage s into buffer bufi ----
    auto prefetch = [&](int s, int bufi) {
        int ch = s % NCH;
        int pr = s / NCH;
        int dd = d0 + pr % nd;
        int tt = t0 + pr / nd;
        int kt = tt - t + 1, kd = dd - d + 1;
        uint32_t xb = sbase + (uint32_t)(bufi * BUF) * 4u;
        uint32_t wb = xb + XS * 4u;
        // X: CI channels of 18x18 haloed plane (zero-fill via src-size 0)
        for (int idx = tid; idx < XS; idx += 128) {
            int ci = idx / 324;
            int rr = idx - ci * 324;
            int r = rr / 18, c2 = rr - r * 18;
            int hh = r - 1, ww = c2 - 1;
            int c = ch * CI + ci;
            const float* sp = (CIN == 64 && c >= 32)
                ? (src1 + (((size_t)(b * 32 + (c - 32))) << 16))
                : (src0 + (((size_t)(b * 32 + (c & 31))) << 16));
            bool ok = ((unsigned)hh < 16u) & ((unsigned)ww < 16u);
            const float* gp = ok ? (sp + ((tt << 12) + (dd << 8) + (hh << 4) + ww)) : sp;
            cpa4(xb + (uint32_t)idx * 4u, gp, ok ? 4 : 0);
        }
        // W: reorder co-innermost for broadcast LDS.128 in compute
        for (int idx = tid; idx < WS; idx += 128) {
            int co = idx & 31;
            int r = idx >> 5;
            int kw = r % 3;
            int kh = (r / 3) % 3;
            int ci = r / 9;
            int c = ch * CI + ci;
            cpa4(wb + (uint32_t)idx * 4u,
                 wgt + ((size_t)co * CIN + c) * 81 + kt * 27 + kd * 9 + kh * 3 + kw, 4);
        }
    };

    // ---- pipeline: prefetch(s+1) overlaps compute(s) ----
    prefetch(0, 0);
    CP_COMMIT();

#pragma unroll 1
    for (int s = 0; s < NST; s++) {
        __syncthreads();                 // buffer (s+1)&1 free (compute s-1 done)
        if (s + 1 < NST) prefetch(s + 1, (s + 1) & 1);
        CP_COMMIT();                     // always commit (possibly empty group)
        CP_WAIT1();                      // stage s deposits (this thread) done
        __syncthreads();                 // all threads' deposits visible

        const float* Xs = S + (s & 1) * BUF;
        const float* Ws = Xs + XS;
#pragma unroll 1
        for (int ci = 0; ci < CI; ci++) {
            const float* xb = Xs + ci * 324 + h * 18 + w;
            const float* wb = Ws + ci * 9 * 32;
#pragma unroll
            for (int kh = 0; kh < 3; kh++) {
#pragma unroll
                for (int kw = 0; kw < 3; kw++) {
                    float xv0 = xb[kh * 18 + kw];
                    float xv1 = xb[kh * 18 + kw + 144];   // (h+8) row
                    unsigned long long xx0 = pack2(xv0, xv0);
                    unsigned long long xx1 = pack2(xv1, xv1);
                    const ulonglong2* wp = (const ulonglong2*)(wb + (kh * 3 + kw) * 32);
#pragma unroll
                    for (int q = 0; q < 8; q++) {
                        ulonglong2 wv = wp[q];
                        fma2(accA[2 * q],     xx0, wv.x);
                        fma2(accA[2 * q + 1], xx0, wv.y);
                        fma2(accB[2 * q],     xx1, wv.x);
                        fma2(accB[2 * q + 1], xx1, wv.y);
                    }
                }
            }
        }
    }

    int pos = (h << 4) + w;      // second position = pos + 128

    if constexpr (SKIP) {
        // Fused 1x1 conv over the 64-channel concat (reuses S)
#pragma unroll 1
        for (int ch = 0; ch < 4; ch++) {
            __syncthreads();
            for (int idx = tid; idx < 16 * 256; idx += 128) {
                int ci = idx >> 8, p = idx & 255;
                int c = ch * 16 + ci;
                const float* sp = (c < 32)
                    ? (sk0 + (((size_t)(b * 32 + c)) << 16))
                    : (sk1 + (((size_t)(b * 32 + c - 32)) << 16));
                S[idx] = sp[(t << 12) + (d << 8) + p];
            }
            for (int idx = tid; idx < 512; idx += 128) {
                int ci = idx >> 5, co = idx & 31;
                S[16 * 256 + idx] = w3[co * 64 + ch * 16 + ci];
            }
            __syncthreads();
#pragma unroll 1
            for (int ci = 0; ci < 16; ci++) {
                float xv0 = S[(ci << 8) + pos];
                float xv1 = S[(ci << 8) + pos + 128];
                unsigned long long xx0 = pack2(xv0, xv0);
                unsigned long long xx1 = pack2(xv1, xv1);
                const ulonglong2* wp = (const ulonglong2*)(S + 16 * 256 + (ci << 5));
#pragma unroll
                for (int q = 0; q < 8; q++) {
                    ulonglong2 wv = wp[q];
                    fma2(accA[2 * q],     xx0, wv.x);
                    fma2(accA[2 * q + 1], xx0, wv.y);
                    fma2(accB[2 * q],     xx1, wv.x);
                    fma2(accB[2 * q + 1], xx1, wv.y);
                }
            }
        }
    }

    size_t obase = ((size_t)b * 32) << 16;
    int opos = (t << 12) + (d << 8) + pos;
#pragma unroll
    for (int j = 0; j < 16; j++) {
        float a0, a1, c0, c1;
        unpack2(accA[j], a0, a1);
        unpack2(accB[j], c0, c1);
        a0 = fmaxf(a0, 0.f); a1 = fmaxf(a1, 0.f);
        c0 = fmaxf(c0, 0.f); c1 = fmaxf(c1, 0.f);
        size_t o0 = obase + (((size_t)(2 * j)) << 16) + opos;
        size_t o1 = obase + (((size_t)(2 * j + 1)) << 16) + opos;
        out[o0]       = a0;
        out[o1]       = a1;
        out[o0 + 128] = c0;   // (h+8) position
        out[o1 + 128] = c1;
    }
}

extern "C" void kernel_launch(void* const* d_in, const int* in_sizes, int n_in,
                              void* d_out, int out_size)
{
    const float* x1   = (const float*)d_in[0];
    const float* x2   = (const float*)d_in[1];
    const float* up_w = (const float*)d_in[2];
    const float* up_b = (const float*)d_in[3];
    const float* w1   = (const float*)d_in[4];
    const float* b1   = (const float*)d_in[5];
    const float* w2   = (const float*)d_in[6];
    const float* b2   = (const float*)d_in[7];
    const float* w3   = (const float*)d_in[8];
    const float* b3   = (const float*)d_in[9];
    float* out = (float*)d_out;

    float *px1u = nullptr, *py1 = nullptr;
    cudaGetSymbolAddress((void**)&px1u, g_x1u);
    cudaGetSymbolAddress((void**)&py1,  g_y1);

    // 1) upsample x1 -> g_x1u (second half of channel concat)
    upconv_kernel<<<1024, 256>>>(x1, up_w, up_b);

    // 2) Y1 = relu(conv4d(concat, w1, b1, pad=1)) -> g_y1
    conv_kernel<64, false><<<dim3(256, 2), 128>>>(
        x2, px1u, w1, b1, nullptr, nullptr, nullptr, nullptr, py1);

    // 3) out = relu(conv4d(Y1, w2, b2, pad=1) + conv1x1(concat, w3, b3))
    conv_kernel<32, true><<<dim3(256, 2), 128>>>(
        py1, nullptr, w2, b2, x2, px1u, w3, b3, out);
}

// round 7
// speedup vs baseline: 2.2661x; 2.2587x over previous
#include <cuda_runtime.h>
#include <cuda_bf16.h>
#include <cstdint>

// Shapes (fixed):
//  x1  [2,64,8,8,8,8]   x2 [2,32,16,16,16,16]
//  up_w[64,32,2,2,2,2]  up_b[32]
//  w1  [32,64,3,3,3,3]  b1[32]
//  w2  [32,32,3,3,3,3]  b2[32]
//  w3  [32,64]          b3[32]
//  out [2,32,16,16,16,16] fp32
//
// Strategy: implicit GEMM on the bf16 warp-MMA path (mma.sync.m16n8k16 —
// plain sm_80+ PTX; tcgen05 is rejected by this toolchain's sm_103 target).
// Split-bf16 hi/lo with 3 MMA passes recovers ~fp32 accuracy (~1e-5).
// Activations live in channels-last, spatially padded (18^4) scratch so every
// im2col row for any tap is a contiguous channel vector.

#define F18 104976   // 18^4
#define C18 5832     // 18^3
#define S18 324      // 18^2

// ---- scratch (device globals; no allocation APIs allowed) ----
__device__ __nv_bfloat16 g_xcH[2 * F18 * 64];
__device__ __nv_bfloat16 g_xcL[2 * F18 * 64];
__device__ __nv_bfloat16 g_y1H[2 * F18 * 32];
__device__ __nv_bfloat16 g_y1L[2 * F18 * 32];
__device__ __nv_bfloat16 g_w1H[81 * 32 * 64];
__device__ __nv_bfloat16 g_w1L[81 * 32 * 64];
__device__ __nv_bfloat16 g_w2H[81 * 32 * 32];
__device__ __nv_bfloat16 g_w2L[81 * 32 * 32];
__device__ __nv_bfloat16 g_w3H[2 * 32 * 32];
__device__ __nv_bfloat16 g_w3L[2 * 32 * 32];

// ---- helpers ----
__device__ __forceinline__ uint32_t smem_u32(const void* p) {
    return (uint32_t)__cvta_generic_to_shared(p);
}
__device__ __forceinline__ void cp16(uint32_t dst, const void* src) {
    asm volatile("cp.async.cg.shared.global [%0], [%1], 16;" :: "r"(dst), "l"(src) : "memory");
}
#define CP_COMMIT() asm volatile("cp.async.commit_group;" ::: "memory")
#define CP_WAIT1()  asm volatile("cp.async.wait_group 1;"  ::: "memory")

// Warp MMA: D[16,8] f32 += A[16,16] bf16 (row) * B[16,8] bf16 (col)
__device__ __forceinline__ void mma_bf16(float* d, const uint32_t* a, const uint32_t* b) {
    asm volatile(
        "mma.sync.aligned.m16n8k16.row.col.f32.bf16.bf16.f32 "
        "{%0,%1,%2,%3}, {%4,%5,%6,%7}, {%8,%9}, {%0,%1,%2,%3};"
        : "+f"(d[0]), "+f"(d[1]), "+f"(d[2]), "+f"(d[3])
        : "r"(a[0]), "r"(a[1]), "r"(a[2]), "r"(a[3]), "r"(b[0]), "r"(b[1]));
}

__device__ __forceinline__ void bsplit(float v, __nv_bfloat16& hi, __nv_bfloat16& lo) {
    hi = __float2bfloat16_rn(v);
    lo = __float2bfloat16_rn(v - __bfloat162float(hi));
}
__device__ __forceinline__ uint32_t pack_bf(__nv_bfloat16 a, __nv_bfloat16 b) {
    return (uint32_t)__bfloat16_as_ushort(a) | ((uint32_t)__bfloat16_as_ushort(b) << 16);
}

// ---------------------------------------------------------------------------
// Prep kernels
// ---------------------------------------------------------------------------
__global__ void zero_pads() {
    size_t tid = (size_t)blockIdx.x * blockDim.x + threadIdx.x;
    size_t stride = (size_t)gridDim.x * blockDim.x;
    uint4 z = {0, 0, 0, 0};
    const size_t nxc = (size_t)2 * F18 * 64 / 8;
    for (size_t i = tid; i < nxc; i += stride) {
        ((uint4*)g_xcH)[i] = z; ((uint4*)g_xcL)[i] = z;
    }
    const size_t ny1 = (size_t)2 * F18 * 32 / 8;
    for (size_t i = tid; i < ny1; i += stride) {
        ((uint4*)g_y1H)[i] = z; ((uint4*)g_y1L)[i] = z;
    }
}

// upsample x1 + concat with x2 -> padded channels-last xc (hi/lo)
__global__ __launch_bounds__(256) void pack_kernel(
    const float* __restrict__ x1, const float* __restrict__ x2,
    const float* __restrict__ uw, const float* __restrict__ ub)
{
    int bx = blockIdx.x;
    int b = bx >> 8, t = (bx >> 4) & 15, d = bx & 15;
    int tid = threadIdx.x;
    int h = tid >> 4, w = tid & 15;

    float acc[32];
#pragma unroll
    for (int co = 0; co < 32; co++) acc[co] = ub[co];

    int sub = ((t & 1) << 3) | ((d & 1) << 2) | ((h & 1) << 1) | (w & 1);
    const float* xp = x1 + (((size_t)b * 64) << 12) + ((t >> 1) << 9) + ((d >> 1) << 6) + ((h >> 1) << 3) + (w >> 1);
#pragma unroll 4
    for (int ci = 0; ci < 64; ci++) {
        float xv = xp[(size_t)ci << 12];
        const float* wr = uw + ((size_t)ci << 9) + sub;
#pragma unroll
        for (int co = 0; co < 32; co++) acc[co] += xv * wr[co << 4];
    }

    size_t ridx = (size_t)b * F18 + (size_t)(t + 1) * C18 + (d + 1) * S18 + (h + 1) * 18 + (w + 1);
    __nv_bfloat16* oh = g_xcH + ridx * 64;
    __nv_bfloat16* ol = g_xcL + ridx * 64;
    int pos = (t << 12) + (d << 8) + (h << 4) + w;
#pragma unroll
    for (int c = 0; c < 32; c++) {
        float v = x2[(((size_t)(b * 32 + c)) << 16) + pos];
        bsplit(v, oh[c], ol[c]);
    }
#pragma unroll
    for (int co = 0; co < 32; co++) {
        bsplit(acc[co], oh[32 + co], ol[32 + co]);
    }
}

// weights -> [tap][co][ci] bf16 hi/lo
__global__ void wprep_kernel(const float* __restrict__ w1, const float* __restrict__ w2,
                             const float* __restrict__ w3)
{
    int i = blockIdx.x * blockDim.x + threadIdx.x;
    int stride = gridDim.x * blockDim.x;
    for (; i < 81 * 32 * 64 + 81 * 32 * 32 + 2 * 32 * 32; i += stride) {
        if (i < 81 * 32 * 64) {
            int tp = i >> 11, rem = i & 2047;
            int co = rem >> 6, ci = rem & 63;
            bsplit(w1[((size_t)(co * 64 + ci)) * 81 + tp], g_w1H[i], g_w1L[i]);
        } else if (i < 81 * 32 * 64 + 81 * 32 * 32) {
            int j = i - 81 * 32 * 64;
            int tp = j >> 10, rem = j & 1023;
            int co = rem >> 5, ci = rem & 31;
            bsplit(w2[((size_t)(co * 32 + ci)) * 81 + tp], g_w2H[j], g_w2L[j]);
        } else {
            int k = i - 81 * 32 * 64 - 81 * 32 * 32;
            int half = k >> 10, rem = k & 1023;
            int co = rem >> 5, ci = rem & 31;
            bsplit(w3[co * 64 + half * 32 + ci], g_w3H[k], g_w3L[k]);
        }
    }
}

// ---------------------------------------------------------------------------
// Warp-MMA conv kernel.
//  CONV=1: xc(64ch) * w1, 81 tap-stages, epilogue relu(+b1) -> y1 hi/lo
//  CONV=2: y1(32ch) * w2, 81 tap-stages + 2 skip stages (xc halves * w3),
//          epilogue relu(+b2+b3) -> fp32 NCHW out
// One CTA per M=128-position tile (b, t, d, half-plane); 8 warps; each warp
// owns an m16 slice x all N=32. Smem rows use a 16B-rotation swizzle so all
// fragment LDS.b32 are bank-conflict-free. Double-buffered cp.async stages.
// ---------------------------------------------------------------------------
template <int CONV>
__global__ __launch_bounds__(256) void conv_mma(
    const __nv_bfloat16* __restrict__ aH, const __nv_bfloat16* __restrict__ aL,
    const __nv_bfloat16* __restrict__ wH, const __nv_bfloat16* __restrict__ wL,
    const __nv_bfloat16* __restrict__ sH, const __nv_bfloat16* __restrict__ sL,
    const __nv_bfloat16* __restrict__ w3H, const __nv_bfloat16* __restrict__ w3L,
    const float* __restrict__ bias0, const float* __restrict__ bias1,
    __nv_bfloat16* __restrict__ outHi, __nv_bfloat16* __restrict__ outLo,
    float* __restrict__ outF)
{
    constexpr int KC     = (CONV == 1) ? 64 : 32;   // K per stage
    constexpr int CPR    = (KC * 2) / 16;           // 16B chunks per row (8/4)
    constexpr int KSTEPS = KC / 16;
    constexpr int NS     = (CONV == 1) ? 81 : 83;
    constexpr int ASPL   = 128 * 128;               // A split plane (uniform 128B pitch)
    constexpr int BSPL   = 32 * 128;
    constexpr int BOFF   = 2 * ASPL;
    constexpr int BUF    = BOFF + 2 * BSPL;         // 40960 B
    constexpr int ACH    = 128 * CPR;
    constexpr int BCH    = 32 * CPR;
    constexpr int CHT    = 2 * (ACH + BCH);         // chunks per stage

    extern __shared__ __align__(128) char smem[];
    uint32_t sb0 = smem_u32(smem);

    int bx  = blockIdx.x;
    int hp  = bx & 1;
    int d   = (bx >> 1) & 15;
    int t   = (bx >> 5) & 15;
    int b   = bx >> 9;
    int tid = threadIdx.x;
    int wid = tid >> 5;
    int lane = tid & 31;
    int lr = lane >> 2, lc = lane & 3;
    int wbase = wid << 4;
    int hp8 = hp << 3;
    size_t bOff = (size_t)b * F18;

    float acc[4][4];
#pragma unroll
    for (int j = 0; j < 4; j++)
#pragma unroll
        for (int e = 0; e < 4; e++) acc[j][e] = 0.f;

    // ---- stage copy: all 256 threads issue cp.asyncs for stage s ----
    auto stage_copy = [&](int s, int bufi) {
        int kt, kd, kh, kw, chbase, srcch;
        const __nv_bfloat16 *srcH_, *srcL_, *wsH, *wsL;
        if (CONV == 2 && s >= 81) {
            int half = s - 81;
            kt = kd = kh = kw = 1;
            srcH_ = sH; srcL_ = sL; srcch = 64; chbase = half << 5;
            wsH = w3H + (half << 10); wsL = w3L + (half << 10);
        } else {
            kt = s / 27; kd = (s / 9) % 3; kh = (s / 3) % 3; kw = s % 3;
            srcH_ = aH; srcL_ = aL; srcch = KC; chbase = 0;
            wsH = wH + (size_t)s * 32 * KC; wsL = wL + (size_t)s * 32 * KC;
        }
        uint32_t sb = sb0 + (uint32_t)bufi * BUF;
#pragma unroll
        for (int ii = 0; ii < CHT / 256; ii++) {
            int i = tid + ii * 256;
            if (i < 2 * ACH) {
                int pl = i >= ACH;
                int a  = i - pl * ACH;
                int r  = a / CPR, c = a % CPR;     // r = m-row, c = chunk
                int hh = hp8 + (r >> 4) + kh;
                int ww = (r & 15) + kw;
                size_t ridx = bOff + (size_t)(t + kt) * C18 + (d + kd) * S18 + hh * 18 + ww;
                const __nv_bfloat16* g = (pl ? srcL_ : srcH_) + ridx * srcch + chbase + c * 8;
                uint32_t dst = sb + pl * ASPL + r * 128 + (((c * 16) + 16 * (r & 7)) & 127);
                cp16(dst, g);
            } else {
                int jj = i - 2 * ACH;
                int pl = jj >= BCH;
                int e  = jj - pl * BCH;
                int r  = e / CPR, c = e % CPR;     // r = co-row
                const __nv_bfloat16* g = (pl ? wsL : wsH) + r * KC + c * 8;
                uint32_t dst = sb + BOFF + pl * BSPL + r * 128 + (((c * 16) + 16 * (r & 7)) & 127);
                cp16(dst, g);
            }
        }
    };

    stage_copy(0, 0);
    CP_COMMIT();

#pragma unroll 1
    for (int s = 0; s < NS; s++) {
        __syncthreads();                 // compute(s-1) done -> buffer (s+1)&1 free
        if (s + 1 < NS) stage_copy(s + 1, (s + 1) & 1);
        CP_COMMIT();
        CP_WAIT1();                      // stage s deposits (this thread) landed
        __syncthreads();                 // all threads' deposits visible

        const char* Sb   = smem + (s & 1) * BUF;
        const char* Arow = Sb + (wbase + lr) * 128;
        const char* Brow = Sb + BOFF + lr * 128;

#pragma unroll
        for (int ks = 0; ks < KSTEPS; ks++) {
            int b0 = ks * 32 + lc * 4;
            int r0 = (b0 + 16 * lr) & 127;
            int r2 = (b0 + 16 + 16 * lr) & 127;

            uint32_t ah[4], al4[4];
            ah[0]  = *(const uint32_t*)(Arow + r0);
            ah[1]  = *(const uint32_t*)(Arow + 8 * 128 + r0);
            ah[2]  = *(const uint32_t*)(Arow + r2);
            ah[3]  = *(const uint32_t*)(Arow + 8 * 128 + r2);
            al4[0] = *(const uint32_t*)(Arow + ASPL + r0);
            al4[1] = *(const uint32_t*)(Arow + ASPL + 8 * 128 + r0);
            al4[2] = *(const uint32_t*)(Arow + ASPL + r2);
            al4[3] = *(const uint32_t*)(Arow + ASPL + 8 * 128 + r2);

#pragma unroll
            for (int j = 0; j < 4; j++) {
                const char* bp = Brow + j * 1024;
                uint32_t bh[2], bl[2];
                bh[0] = *(const uint32_t*)(bp + r0);
                bh[1] = *(const uint32_t*)(bp + r2);
                bl[0] = *(const uint32_t*)(bp + BSPL + r0);
                bl[1] = *(const uint32_t*)(bp + BSPL + r2);
                mma_bf16(acc[j], ah,  bh);   // hi*hi
                mma_bf16(acc[j], al4, bh);   // lo*hi
                mma_bf16(acc[j], ah,  bl);   // hi*lo
            }
        }
    }

    // ---- epilogue ----
    float bb0[4], bb1[4];
#pragma unroll
    for (int j = 0; j < 4; j++) {
        int co = 8 * j + 2 * lc;
        bb0[j] = bias0[co]     + ((CONV == 2) ? bias1[co]     : 0.f);
        bb1[j] = bias0[co + 1] + ((CONV == 2) ? bias1[co + 1] : 0.f);
    }

#pragma unroll
    for (int rr = 0; rr < 2; rr++) {
        int m = wbase + lr + rr * 8;
        int h = hp8 + (m >> 4);
        int w = m & 15;
        if (CONV == 1) {
            size_t ridx = bOff + (size_t)(t + 1) * C18 + (d + 1) * S18 + (h + 1) * 18 + (w + 1);
            uint32_t* oh = (uint32_t*)(outHi + ridx * 32);
            uint32_t* ol = (uint32_t*)(outLo + ridx * 32);
#pragma unroll
            for (int j = 0; j < 4; j++) {
                float v0 = fmaxf(acc[j][rr * 2 + 0] + bb0[j], 0.f);
                float v1 = fmaxf(acc[j][rr * 2 + 1] + bb1[j], 0.f);
                __nv_bfloat16 h0, l0, h1, l1;
                bsplit(v0, h0, l0);
                bsplit(v1, h1, l1);
                oh[4 * j + lc] = pack_bf(h0, h1);
                ol[4 * j + lc] = pack_bf(l0, l1);
            }
        } else {
            size_t obase = ((size_t)b * 32) << 16;
            int opos = (t << 12) + (d << 8) + (h << 4) + w;
#pragma unroll
            for (int j = 0; j < 4; j++) {
                int co = 8 * j + 2 * lc;
                float v0 = fmaxf(acc[j][rr * 2 + 0] + bb0[j], 0.f);
                float v1 = fmaxf(acc[j][rr * 2 + 1] + bb1[j], 0.f);
                outF[obase + (((size_t)co) << 16) + opos]       = v0;
                outF[obase + (((size_t)(co + 1)) << 16) + opos] = v1;
            }
        }
    }
}

// ---------------------------------------------------------------------------
extern "C" void kernel_launch(void* const* d_in, const int* in_sizes, int n_in,
                              void* d_out, int out_size)
{
    const float* x1   = (const float*)d_in[0];
    const float* x2   = (const float*)d_in[1];
    const float* up_w = (const float*)d_in[2];
    const float* up_b = (const float*)d_in[3];
    const float* w1   = (const float*)d_in[4];
    const float* b1   = (const float*)d_in[5];
    const float* w2   = (const float*)d_in[6];
    const float* b2   = (const float*)d_in[7];
    const float* w3   = (const float*)d_in[8];
    const float* b3   = (const float*)d_in[9];
    float* out = (float*)d_out;

    __nv_bfloat16 *xcH, *xcL, *y1H, *y1L, *w1H, *w1L, *w2H, *w2L, *w3H, *w3L;
    cudaGetSymbolAddress((void**)&xcH, g_xcH);
    cudaGetSymbolAddress((void**)&xcL, g_xcL);
    cudaGetSymbolAddress((void**)&y1H, g_y1H);
    cudaGetSymbolAddress((void**)&y1L, g_y1L);
    cudaGetSymbolAddress((void**)&w1H, g_w1H);
    cudaGetSymbolAddress((void**)&w1L, g_w1L);
    cudaGetSymbolAddress((void**)&w2H, g_w2H);
    cudaGetSymbolAddress((void**)&w2L, g_w2L);
    cudaGetSymbolAddress((void**)&w3H, g_w3H);
    cudaGetSymbolAddress((void**)&w3L, g_w3L);

    constexpr int SMB = 2 * (2 * 128 * 128 + 2 * 32 * 128);  // 81920 bytes
    cudaFuncSetAttribute(conv_mma<1>, cudaFuncAttributeMaxDynamicSharedMemorySize, SMB);
    cudaFuncSetAttribute(conv_mma<2>, cudaFuncAttributeMaxDynamicSharedMemorySize, SMB);

    zero_pads<<<2048, 256>>>();
    pack_kernel<<<512, 256>>>(x1, x2, up_w, up_b);
    wprep_kernel<<<512, 256>>>(w1, w2, w3);

    // conv1: y1 = relu(conv(xc, w1) + b1)
    conv_mma<1><<<1024, 256, SMB>>>(
        xcH, xcL, w1H, w1L, nullptr, nullptr, nullptr, nullptr,
        b1, nullptr, y1H, y1L, nullptr);

    // conv2: out = relu(conv(y1, w2) + b2 + conv1x1(xc, w3) + b3)
    conv_mma<2><<<1024, 256, SMB>>>(
        y1H, y1L, w2H, w2L, xcH, xcL, w3H, w3L,
        b2, b3, nullptr, nullptr, out);
}

// round 9
// speedup vs baseline: 3.0034x; 1.3254x over previous
#include <cuda_runtime.h>
#include <cuda_fp16.h>
#include <cstdint>

// Shapes (fixed):
//  x1  [2,64,8,8,8,8]   x2 [2,32,16,16,16,16]
//  up_w[64,32,2,2,2,2]  up_b[32]
//  w1  [32,64,3,3,3,3]  b1[32]
//  w2  [32,32,3,3,3,3]  b2[32]
//  w3  [32,64]          b3[32]
//  out [2,32,16,16,16,16] fp32
//
// Implicit GEMM on mma.sync.m16n8k16 fp16 path.
// Accuracy scheme: activations split-fp16 (hi+lo, ~exact), weights rounded
// to fp16 once -> 2 MMA passes, error ~2e-4 (budget 1e-3).
// Supertap staging: one stage per (kt,kd,kh); the 3 kw taps are fragment
// address shifts into a 144-row staged activation strip.

#define F18 104976   // 18^4
#define C18 5832     // 18^3
#define S18 324      // 18^2

// ---- scratch (device globals; no allocation APIs allowed) ----
__device__ __half g_xcH[2 * F18 * 64];
__device__ __half g_xcL[2 * F18 * 64];
__device__ __half g_y1H[2 * F18 * 32];
__device__ __half g_y1L[2 * F18 * 32];
__device__ __half g_w1F[81 * 32 * 64];
__device__ __half g_w2F[81 * 32 * 32];
__device__ __half g_w3F[2 * 32 * 32];

// ---- helpers ----
__device__ __forceinline__ uint32_t smem_u32(const void* p) {
    return (uint32_t)__cvta_generic_to_shared(p);
}
__device__ __forceinline__ void cp16(uint32_t dst, const void* src) {
    asm volatile("cp.async.cg.shared.global [%0], [%1], 16;" :: "r"(dst), "l"(src) : "memory");
}
#define CP_COMMIT() asm volatile("cp.async.commit_group;" ::: "memory")
#define CP_WAIT1()  asm volatile("cp.async.wait_group 1;"  ::: "memory")

// Warp MMA: D[16,8] f32 += A[16,16] fp16 (row) * B[16,8] fp16 (col)
__device__ __forceinline__ void mma_fp16(float* d, const uint32_t* a, const uint32_t* b) {
    asm volatile(
        "mma.sync.aligned.m16n8k16.row.col.f32.f16.f16.f32 "
        "{%0,%1,%2,%3}, {%4,%5,%6,%7}, {%8,%9}, {%0,%1,%2,%3};"
        : "+f"(d[0]), "+f"(d[1]), "+f"(d[2]), "+f"(d[3])
        : "r"(a[0]), "r"(a[1]), "r"(a[2]), "r"(a[3]), "r"(b[0]), "r"(b[1]));
}

__device__ __forceinline__ void hsplit(float v, __half& hi, __half& lo) {
    hi = __float2half_rn(v);
    lo = __float2half_rn(v - __half2float(hi));
}
__device__ __forceinline__ uint32_t pack_hf(__half a, __half b) {
    return (uint32_t)__half_as_ushort(a) | ((uint32_t)__half_as_ushort(b) << 16);
}

// ---------------------------------------------------------------------------
// Prep kernels
// ---------------------------------------------------------------------------
__global__ void zero_pads() {
    size_t tid = (size_t)blockIdx.x * blockDim.x + threadIdx.x;
    size_t stride = (size_t)gridDim.x * blockDim.x;
    uint4 z = {0, 0, 0, 0};
    const size_t nxc = (size_t)2 * F18 * 64 / 8;   // uint4 count (8 halfs each)
    for (size_t i = tid; i < nxc; i += stride) {
        ((uint4*)g_xcH)[i] = z; ((uint4*)g_xcL)[i] = z;
    }
    const size_t ny1 = (size_t)2 * F18 * 32 / 8;
    for (size_t i = tid; i < ny1; i += stride) {
        ((uint4*)g_y1H)[i] = z; ((uint4*)g_y1L)[i] = z;
    }
}

// upsample x1 + concat with x2 -> padded channels-last xc (hi/lo fp16)
__global__ __launch_bounds__(256) void pack_kernel(
    const float* __restrict__ x1, const float* __restrict__ x2,
    const float* __restrict__ uw, const float* __restrict__ ub)
{
    int bx = blockIdx.x;
    int b = bx >> 8, t = (bx >> 4) & 15, d = bx & 15;
    int tid = threadIdx.x;
    int h = tid >> 4, w = tid & 15;

    float acc[32];
#pragma unroll
    for (int co = 0; co < 32; co++) acc[co] = ub[co];

    int sub = ((t & 1) << 3) | ((d & 1) << 2) | ((h & 1) << 1) | (w & 1);
    const float* xp = x1 + (((size_t)b * 64) << 12) + ((t >> 1) << 9) + ((d >> 1) << 6) + ((h >> 1) << 3) + (w >> 1);
#pragma unroll 4
    for (int ci = 0; ci < 64; ci++) {
        float xv = xp[(size_t)ci << 12];
        const float* wr = uw + ((size_t)ci << 9) + sub;
#pragma unroll
        for (int co = 0; co < 32; co++) acc[co] += xv * wr[co << 4];
    }

    size_t ridx = (size_t)b * F18 + (size_t)(t + 1) * C18 + (d + 1) * S18 + (h + 1) * 18 + (w + 1);
    __half* oh = g_xcH + ridx * 64;
    __half* ol = g_xcL + ridx * 64;
    int pos = (t << 12) + (d << 8) + (h << 4) + w;
#pragma unroll
    for (int c = 0; c < 32; c++) {
        float v = x2[(((size_t)(b * 32 + c)) << 16) + pos];
        hsplit(v, oh[c], ol[c]);
    }
#pragma unroll
    for (int co = 0; co < 32; co++) {
        hsplit(acc[co], oh[32 + co], ol[32 + co]);
    }
}

// weights -> [tap81][co][ci] fp16 (rounded once)
__global__ void wprep_kernel(const float* __restrict__ w1, const float* __restrict__ w2,
                             const float* __restrict__ w3)
{
    int i = blockIdx.x * blockDim.x + threadIdx.x;
    int stride = gridDim.x * blockDim.x;
    for (; i < 81 * 32 * 64 + 81 * 32 * 32 + 2 * 32 * 32; i += stride) {
        if (i < 81 * 32 * 64) {
            int tp = i >> 11, rem = i & 2047;
            int co = rem >> 6, ci = rem & 63;
            g_w1F[i] = __float2half_rn(w1[((size_t)(co * 64 + ci)) * 81 + tp]);
        } else if (i < 81 * 32 * 64 + 81 * 32 * 32) {
            int j = i - 81 * 32 * 64;
            int tp = j >> 10, rem = j & 1023;
            int co = rem >> 5, ci = rem & 31;
            g_w2F[j] = __float2half_rn(w2[((size_t)(co * 32 + ci)) * 81 + tp]);
        } else {
            int k = i - 81 * 32 * 64 - 81 * 32 * 32;
            int half_ = k >> 10, rem = k & 1023;
            int co = rem >> 5, ci = rem & 31;
            g_w3F[k] = __float2half_rn(w3[co * 64 + half_ * 32 + ci]);
        }
    }
}

// ---------------------------------------------------------------------------
// Supertap warp-MMA conv kernel.
//  CONV=1: xc(64ch)*w1, 27 stages (kt,kd,kh), relu(+b1) -> y1 hi/lo
//  CONV=2: y1(32ch)*w2, 27 stages + 2 skip stages (xc halves * w3),
//          relu(+b2+b3) -> fp32 NCHW out
// A plane per stage: 144 rows = (hrel 0..7)x(w' 0..17), hi+lo planes.
// B per stage: 3 kw taps x 32 co rows, single fp16 plane.
// 8 warps: warp = m16 slice (hrel=wid's h-row pair), all N=32 couts.
// 128B row pitch + 16B rotation swizzle -> conflict-free fragment LDS.
// ---------------------------------------------------------------------------
template <int CONV>
__global__ __launch_bounds__(256) void conv_mma(
    const __half* __restrict__ aH, const __half* __restrict__ aL,
    const __half* __restrict__ wF,
    const __half* __restrict__ sH, const __half* __restrict__ sL,
    const __half* __restrict__ w3F,
    const float* __restrict__ bias0, const float* __restrict__ bias1,
    __half* __restrict__ outHi, __half* __restrict__ outLo,
    float* __restrict__ outF)
{
    constexpr int KC     = (CONV == 1) ? 64 : 32;   // K per tap
    constexpr int CPR    = KC / 8;                  // 16B chunks per row (8/4)
    constexpr int KSTEPS = KC / 16;                 // 4 / 2
    constexpr int NS     = (CONV == 1) ? 27 : 29;   // stages
    constexpr int ASPL   = 144 * 128;               // A plane bytes (one split)
    constexpr int BOFF   = 2 * ASPL;
    constexpr int BSZ    = 3 * 32 * 128;            // B (3 taps x 32 co rows)
    constexpr int BUF    = BOFF + BSZ;              // 49152
    constexpr int ACH    = 144 * CPR;               // chunks per A plane
    constexpr int BCH    = 32 * CPR;                // chunks per B tap
    constexpr int CHT    = 2 * ACH + 3 * BCH;       // chunk slots per stage

    extern __shared__ __align__(128) char smem[];
    uint32_t sb0 = smem_u32(smem);

    int bx  = blockIdx.x;
    int hp  = bx & 1;
    int d   = (bx >> 1) & 15;
    int t   = (bx >> 5) & 15;
    int b   = bx >> 9;
    int tid = threadIdx.x;
    int wid = tid >> 5;
    int lane = tid & 31;
    int lr = lane >> 2, lc = lane & 3;
    int hp8 = hp << 3;
    size_t bOff = (size_t)b * F18;

    float acc[4][4];
#pragma unroll
    for (int j = 0; j < 4; j++)
#pragma unroll
        for (int e = 0; e < 4; e++) acc[j][e] = 0.f;

    // ---- stage copy: all 256 threads issue cp.asyncs for stage s ----
    auto stage_copy = [&](int s, int bufi) {
        int kt, kd, kh, chbase, srcch, ntap;
        const __half *srcH_, *srcL_, *wsrc;
        if (CONV == 2 && s >= 27) {
            int half_ = s - 27;
            kt = kd = kh = 1;
            srcH_ = sH; srcL_ = sL; srcch = 64; chbase = half_ << 5;
            wsrc = w3F + (half_ << 10);
            ntap = 1;
        } else {
            kt = s / 9; kd = (s / 3) % 3; kh = s % 3;
            srcH_ = aH; srcL_ = aL; srcch = KC; chbase = 0;
            wsrc = wF + (size_t)s * 3 * 32 * KC;   // tap81 = s*3 + tt
            ntap = 3;
        }
        uint32_t sb = sb0 + (uint32_t)bufi * BUF;
        size_t base = bOff + (size_t)(t + kt) * C18 + (size_t)(d + kd) * S18;
#pragma unroll
        for (int ii = 0; ii < CHT / 256; ii++) {
            int i = tid + ii * 256;
            if (i < 2 * ACH) {
                int pl = i >= ACH;
                int a  = i - pl * ACH;
                int pr = a / CPR, c = a % CPR;       // pr = plane row 0..143
                int hrel = pr / 18, wp = pr - hrel * 18;
                size_t ridx = base + (size_t)(hp8 + hrel + kh) * 18 + wp;
                const __half* g = (pl ? srcL_ : srcH_) + ridx * srcch + chbase + c * 8;
                uint32_t dst = sb + pl * ASPL + pr * 128 + (((c * 16) + 16 * (pr & 7)) & 127);
                cp16(dst, g);
            } else {
                int jj = i - 2 * ACH;
                int tt = jj / BCH;
                int e  = jj - tt * BCH;
                int r  = e / CPR, c = e % CPR;       // r = co row
                if (tt < ntap) {
                    const __half* g = wsrc + tt * 32 * KC + r * KC + c * 8;
                    uint32_t dst = sb + BOFF + (tt * 32 + r) * 128 + (((c * 16) + 16 * (r & 7)) & 127);
                    cp16(dst, g);
                }
            }
        }
    };

    stage_copy(0, 0);
    CP_COMMIT();

#pragma unroll 1
    for (int s = 0; s < NS; s++) {
        __syncthreads();                 // compute(s-1) done -> buffer (s+1)&1 free
        if (s + 1 < NS) stage_copy(s + 1, (s + 1) & 1);
        CP_COMMIT();
        CP_WAIT1();                      // stage s deposits landed (this thread)
        __syncthreads();                 // all threads' deposits visible

        const char* Sb = smem + (s & 1) * BUF;
        const char* Ah = Sb;
        const char* Al = Sb + ASPL;
        const char* Bp = Sb + BOFF;

        int kw0 = (CONV == 2 && s >= 27) ? 1 : 0;
        int nkw = (CONV == 2 && s >= 27) ? 1 : 3;

#pragma unroll 1
        for (int kwi = 0; kwi < nkw; kwi++) {
            int kw = kw0 + kwi;
            int rA0 = wid * 18 + lr + kw;      // plane row for m-row (wid, lr)
            int rotA = 16 * (rA0 & 7);          // rA0+8 has same &7
            const char* a0p = Ah + rA0 * 128;
            const char* a1p = a0p + 8 * 128;    // row rA0+8
            const char* l0p = Al + rA0 * 128;
            const char* l1p = l0p + 8 * 128;
            const char* bbase = Bp + kwi * 32 * 128 + lr * 128;
            int rotB = 16 * lr;

#pragma unroll
            for (int ks = 0; ks < KSTEPS; ks++) {
                int off = ks * 32 + lc * 4;
                int oA0 = (off + rotA) & 127;
                int oA1 = (off + 16 + rotA) & 127;

                uint32_t ah[4], al4[4];
                ah[0]  = *(const uint32_t*)(a0p + oA0);
                ah[1]  = *(const uint32_t*)(a1p + oA0);
                ah[2]  = *(const uint32_t*)(a0p + oA1);
                ah[3]  = *(const uint32_t*)(a1p + oA1);
                al4[0] = *(const uint32_t*)(l0p + oA0);
                al4[1] = *(const uint32_t*)(l1p + oA0);
                al4[2] = *(const uint32_t*)(l0p + oA1);
                al4[3] = *(const uint32_t*)(l1p + oA1);

                int oB0 = (off + rotB) & 127;
                int oB1 = (off + 16 + rotB) & 127;
#pragma unroll
                for (int j = 0; j < 4; j++) {
                    const char* bp = bbase + j * 1024;
                    uint32_t bf[2];
                    bf[0] = *(const uint32_t*)(bp + oB0);
                    bf[1] = *(const uint32_t*)(bp + oB1);
                    mma_fp16(acc[j], ah,  bf);   // Ah * Bh
                    mma_fp16(acc[j], al4, bf);   // Al * Bh
                }
            }
        }
    }

    // ---- epilogue ----
    float bb0[4], bb1[4];
#pragma unroll
    for (int j = 0; j < 4; j++) {
        int co = 8 * j + 2 * lc;
        bb0[j] = bias0[co]     + ((CONV == 2) ? bias1[co]     : 0.f);
        bb1[j] = bias0[co + 1] + ((CONV == 2) ? bias1[co + 1] : 0.f);
    }

#pragma unroll
    for (int rr = 0; rr < 2; rr++) {
        int m = (wid << 4) + lr + rr * 8;
        int h = hp8 + (m >> 4);
        int w = m & 15;
        if (CONV == 1) {
            size_t ridx = bOff + (size_t)(t + 1) * C18 + (d + 1) * S18 + (h + 1) * 18 + (w + 1);
            uint32_t* oh = (uint32_t*)(outHi + ridx * 32);
            uint32_t* ol = (uint32_t*)(outLo + ridx * 32);
#pragma unroll
            for (int j = 0; j < 4; j++) {
                float v0 = fmaxf(acc[j][rr * 2 + 0] + bb0[j], 0.f);
                float v1 = fmaxf(acc[j][rr * 2 + 1] + bb1[j], 0.f);
                __half h0, l0, h1, l1;
                hsplit(v0, h0, l0);
                hsplit(v1, h1, l1);
                oh[4 * j + lc] = pack_hf(h0, h1);
                ol[4 * j + lc] = pack_hf(l0, l1);
            }
        } else {
            size_t obase = ((size_t)b * 32) << 16;
            int opos = (t << 12) + (d << 8) + (h << 4) + w;
#pragma unroll
            for (int j = 0; j < 4; j++) {
                int co = 8 * j + 2 * lc;
                float v0 = fmaxf(acc[j][rr * 2 + 0] + bb0[j], 0.f);
                float v1 = fmaxf(acc[j][rr * 2 + 1] + bb1[j], 0.f);
                outF[obase + (((size_t)co) << 16) + opos]       = v0;
                outF[obase + (((size_t)(co + 1)) << 16) + opos] = v1;
            }
        }
    }
}

// ---------------------------------------------------------------------------
extern "C" void kernel_launch(void* const* d_in, const int* in_sizes, int n_in,
                              void* d_out, int out_size)
{
    const float* x1   = (const float*)d_in[0];
    const float* x2   = (const float*)d_in[1];
    const float* up_w = (const float*)d_in[2];
    const float* up_b = (const float*)d_in[3];
    const float* w1   = (const float*)d_in[4];
    const float* b1   = (const float*)d_in[5];
    const float* w2   = (const float*)d_in[6];
    const float* b2   = (const float*)d_in[7];
    const float* w3   = (const float*)d_in[8];
    const float* b3   = (const float*)d_in[9];
    float* out = (float*)d_out;

    __half *xcH, *xcL, *y1H, *y1L, *w1F, *w2F, *w3F;
    cudaGetSymbolAddress((void**)&xcH, g_xcH);
    cudaGetSymbolAddress((void**)&xcL, g_xcL);
    cudaGetSymbolAddress((void**)&y1H, g_y1H);
    cudaGetSymbolAddress((void**)&y1L, g_y1L);
    cudaGetSymbolAddress((void**)&w1F, g_w1F);
    cudaGetSymbolAddress((void**)&w2F, g_w2F);
    cudaGetSymbolAddress((void**)&w3F, g_w3F);

    constexpr int SMB = 2 * (2 * 144 * 128 + 3 * 32 * 128);  // 98304 bytes
    cudaFuncSetAttribute(conv_mma<1>, cudaFuncAttributeMaxDynamicSharedMemorySize, SMB);
    cudaFuncSetAttribute(conv_mma<2>, cudaFuncAttributeMaxDynamicSharedMemorySize, SMB);

    zero_pads<<<2048, 256>>>();
    pack_kernel<<<512, 256>>>(x1, x2, up_w, up_b);
    wprep_kernel<<<512, 256>>>(w1, w2, w3);

    // conv1: y1 = relu(conv(xc, w1) + b1)
    conv_mma<1><<<1024, 256, SMB>>>(
        xcH, xcL, w1F, nullptr, nullptr, nullptr,
        b1, nullptr, y1H, y1L, nullptr);

    // conv2: out = relu(conv(y1, w2) + b2 + conv1x1(xc, w3) + b3)
    conv_mma<2><<<1024, 256, SMB>>>(
        y1H, y1L, w2F, xcH, xcL, w3F,
        b2, b3, nullptr, nullptr, out);
}

// round 11
// speedup vs baseline: 3.2845x; 1.0936x over previous
#include <cuda_runtime.h>
#include <cuda_fp16.h>
#include <cstdint>

// Shapes (fixed):
//  x1  [2,64,8,8,8,8]   x2 [2,32,16,16,16,16]
//  up_w[64,32,2,2,2,2]  up_b[32]
//  w1  [32,64,3,3,3,3]  b1[32]
//  w2  [32,32,3,3,3,3]  b2[32]
//  w3  [32,64]          b3[32]
//  out [2,32,16,16,16,16] fp32
//
// Implicit GEMM, mma.sync.m16n8k16 fp16, activations split-fp16 (hi+lo,
// 2 passes), weights rounded once. CTA = full (b,t,d) plane (M=256), 8 warps,
// m32 per warp. Stage = (kt,kd) [+ci-half for conv1]: kh,kw are address
// shifts into one staged 18x18 channel-sliced plane.
// Smem rows are 64B slots packed 2-per-128B-line with a line-rotation swizzle
// (conflict-free for fragment loads and staging stores).

#define F18 104976   // 18^4
#define C18 5832     // 18^3
#define S18 324      // 18^2

// ---- scratch (device globals; zero-initialized at module load — halos are
// never written, interiors are fully rewritten every call) ----
__device__ __half g_xcH[2 * F18 * 64];
__device__ __half g_xcL[2 * F18 * 64];
__device__ __half g_y1H[2 * F18 * 32];
__device__ __half g_y1L[2 * F18 * 32];
__device__ __half g_w1F[81 * 32 * 64];
__device__ __half g_w2F[81 * 32 * 32];
__device__ __half g_w3F[2 * 32 * 32];

// ---- helpers ----
__device__ __forceinline__ uint32_t smem_u32(const void* p) {
    return (uint32_t)__cvta_generic_to_shared(p);
}
__device__ __forceinline__ void cp16(uint32_t dst, const void* src) {
    asm volatile("cp.async.cg.shared.global [%0], [%1], 16;" :: "r"(dst), "l"(src) : "memory");
}
#define CP_COMMIT() asm volatile("cp.async.commit_group;" ::: "memory")
#define CP_WAIT1()  asm volatile("cp.async.wait_group 1;"  ::: "memory")

__device__ __forceinline__ void mma_fp16(float* d, const uint32_t* a, const uint32_t* b) {
    asm volatile(
        "mma.sync.aligned.m16n8k16.row.col.f32.f16.f16.f32 "
        "{%0,%1,%2,%3}, {%4,%5,%6,%7}, {%8,%9}, {%0,%1,%2,%3};"
        : "+f"(d[0]), "+f"(d[1]), "+f"(d[2]), "+f"(d[3])
        : "r"(a[0]), "r"(a[1]), "r"(a[2]), "r"(a[3]), "r"(b[0]), "r"(b[1]));
}
__device__ __forceinline__ void hsplit(float v, __half& hi, __half& lo) {
    hi = __float2half_rn(v);
    lo = __float2half_rn(v - __half2float(hi));
}
__device__ __forceinline__ uint32_t pack_hf(__half a, __half b) {
    return (uint32_t)__half_as_ushort(a) | ((uint32_t)__half_as_ushort(b) << 16);
}
// Packed-64B-slot smem offset: row pr (64B of data), byte o within slot (0..63)
__device__ __forceinline__ uint32_t sladdr(int pr, int o) {
    return (uint32_t)(((pr >> 1) << 7) + ((pr & 1) << 6) + ((o + (((pr >> 1) & 3) << 4)) & 63));
}

// ---------------------------------------------------------------------------
// Prep kernels
// ---------------------------------------------------------------------------
// upsample x1 + concat with x2 -> padded channels-last xc (hi/lo fp16)
__global__ __launch_bounds__(256) void pack_kernel(
    const float* __restrict__ x1, const float* __restrict__ x2,
    const float* __restrict__ uw, const float* __restrict__ ub)
{
    int bx = blockIdx.x;
    int b = bx >> 8, t = (bx >> 4) & 15, d = bx & 15;
    int tid = threadIdx.x;
    int h = tid >> 4, w = tid & 15;

    float acc[32];
#pragma unroll
    for (int co = 0; co < 32; co++) acc[co] = ub[co];

    int sub = ((t & 1) << 3) | ((d & 1) << 2) | ((h & 1) << 1) | (w & 1);
    const float* xp = x1 + (((size_t)b * 64) << 12) + ((t >> 1) << 9) + ((d >> 1) << 6) + ((h >> 1) << 3) + (w >> 1);
#pragma unroll 4
    for (int ci = 0; ci < 64; ci++) {
        float xv = xp[(size_t)ci << 12];
        const float* wr = uw + ((size_t)ci << 9) + sub;
#pragma unroll
        for (int co = 0; co < 32; co++) acc[co] += xv * wr[co << 4];
    }

    size_t ridx = (size_t)b * F18 + (size_t)(t + 1) * C18 + (d + 1) * S18 + (h + 1) * 18 + (w + 1);
    __half* oh = g_xcH + ridx * 64;
    __half* ol = g_xcL + ridx * 64;
    int pos = (t << 12) + (d << 8) + (h << 4) + w;
#pragma unroll
    for (int c = 0; c < 32; c++) {
        float v = x2[(((size_t)(b * 32 + c)) << 16) + pos];
        hsplit(v, oh[c], ol[c]);
    }
#pragma unroll
    for (int co = 0; co < 32; co++) {
        hsplit(acc[co], oh[32 + co], ol[32 + co]);
    }
}

// weights -> [tap81][co][ci] fp16 (rounded once)
__global__ void wprep_kernel(const float* __restrict__ w1, const float* __restrict__ w2,
                             const float* __restrict__ w3)
{
    int i = blockIdx.x * blockDim.x + threadIdx.x;
    int stride = gridDim.x * blockDim.x;
    for (; i < 81 * 32 * 64 + 81 * 32 * 32 + 2 * 32 * 32; i += stride) {
        if (i < 81 * 32 * 64) {
            int tp = i >> 11, rem = i & 2047;
            int co = rem >> 6, ci = rem & 63;
            g_w1F[i] = __float2half_rn(w1[((size_t)(co * 64 + ci)) * 81 + tp]);
        } else if (i < 81 * 32 * 64 + 81 * 32 * 32) {
            int j = i - 81 * 32 * 64;
            int tp = j >> 10, rem = j & 1023;
            int co = rem >> 5, ci = rem & 31;
            g_w2F[j] = __float2half_rn(w2[((size_t)(co * 32 + ci)) * 81 + tp]);
        } else {
            int k = i - 81 * 32 * 64 - 81 * 32 * 32;
            int half_ = k >> 10, rem = k & 1023;
            int co = rem >> 5, ci = rem & 31;
            g_w3F[k] = __float2half_rn(w3[co * 64 + half_ * 32 + ci]);
        }
    }
}

// ---------------------------------------------------------------------------
// Conv kernel. M=256 (full plane per (b,t,d)), 8 warps x m32, N=32, KC=32.
//  CONV=1: stages = (kt,kd)x(ci-half) = 18; A = xc 32-ch slice; B = w1 slice.
//  CONV=2: stages = (kt,kd) = 9 over y1 + 2 skip stages (xc halves * w3).
// A plane per stage: 324 rows (18h' x 18w') x 32ch, hi+lo. B: 9 taps x 32 co.
// ---------------------------------------------------------------------------
template <int CONV>
__global__ __launch_bounds__(256) void conv_mma(
    const __half* __restrict__ aH, const __half* __restrict__ aL,
    const __half* __restrict__ wF,
    const __half* __restrict__ sH, const __half* __restrict__ sL,
    const __half* __restrict__ w3F,
    const float* __restrict__ bias0, const float* __restrict__ bias1,
    __half* __restrict__ outHi, __half* __restrict__ outLo,
    float* __restrict__ outF)
{
    constexpr int NS   = (CONV == 1) ? 18 : 11;
    constexpr int APL  = 324 * 64;            // 20736 B per A split plane
    constexpr int AB   = 2 * APL;             // 41472
    constexpr int BB   = 9 * 32 * 64;         // 18432
    constexpr int BUF  = AB + BB;             // 59904
    constexpr int ACH  = 2 * 324 * 4;         // A 16B chunks (hi+lo)
    constexpr int CHT  = ACH + 9 * 32 * 4;    // 3744 chunk slots
    constexpr int WROW = (CONV == 1) ? 64 : 32;  // co stride in source weights
    constexpr int TAPS = 32 * WROW;

    extern __shared__ __align__(128) char smem[];
    uint32_t sb0 = smem_u32(smem);

    int bx  = blockIdx.x;
    int t   = bx >> 4, d = bx & 15;
    int b   = blockIdx.y;
    int tid = threadIdx.x;
    int wid = tid >> 5;
    int lane = tid & 31;
    int lr = lane >> 2, lc = lane & 3;
    size_t bOff = (size_t)b * F18;

    float acc[2][4][4];
#pragma unroll
    for (int mt = 0; mt < 2; mt++)
#pragma unroll
        for (int j = 0; j < 4; j++)
#pragma unroll
            for (int e = 0; e < 4; e++) acc[mt][j][e] = 0.f;

    // ---- stage copy ----
    auto stage_copy = [&](int s, int bufi) {
        int kt, kd, chbase, srcch, ntap;
        const __half *srcH_, *srcL_, *wsrc;
        if (CONV == 2 && s >= 9) {
            int half_ = s - 9;
            kt = 1; kd = 1;
            srcH_ = sH; srcL_ = sL; srcch = 64; chbase = half_ << 5;
            wsrc = w3F + (half_ << 10);
            ntap = 1;
        } else {
            int pair  = (CONV == 1) ? (s >> 1) : s;
            int half_ = (CONV == 1) ? (s & 1) : 0;
            kt = pair / 3; kd = pair % 3;
            srcH_ = aH; srcL_ = aL;
            srcch = (CONV == 1) ? 64 : 32;
            chbase = half_ << 5;
            wsrc = wF + (size_t)(kt * 27 + kd * 9) * TAPS + chbase;  // slice offset (0 for CONV==2)
            ntap = 9;
        }
        uint32_t sb = sb0 + (uint32_t)bufi * BUF;
        size_t abase = bOff + (size_t)(t + kt) * C18 + (size_t)(d + kd) * S18;
#pragma unroll
        for (int ii = 0; ii < 15; ii++) {
            int i = tid + ii * 256;
            if (i < ACH) {
                int pl = i >= 1296;
                int a  = i - (pl ? 1296 : 0);
                int pr = a >> 2, c = a & 3;
                const __half* g = (pl ? srcL_ : srcH_) + (abase + pr) * srcch + chbase + c * 8;
                cp16(sb + pl * APL + sladdr(pr, c << 4), g);
            } else if (i < CHT) {
                int j2 = i - ACH;
                int tt = j2 >> 7;
                int e  = j2 & 127;
                int r  = e >> 2, c = e & 3;
                if (tt < ntap) {
                    const __half* g = wsrc + (size_t)tt * TAPS + r * WROW + c * 8;
                    cp16(sb + AB + sladdr((tt << 5) + r, c << 4), g);
                }
            }
        }
    };

    // ---- compute bundle: one (kh,kw) tap, both ks, both mt, all N ----
    auto bundle = [&](const char* Ab, const char* Bb, int kh, int kw, int tb) {
#pragma unroll
        for (int ks = 0; ks < 2; ks++) {
            int o = (ks << 5) + (lc << 2);
            uint32_t ah[2][4], al[2][4];
#pragma unroll
            for (int mt = 0; mt < 2; mt++) {
                int pr0 = (2 * wid + mt + kh) * 18 + lr + kw;
                int pr1 = pr0 + 8;
                uint32_t a00 = sladdr(pr0, o),      a10 = sladdr(pr1, o);
                uint32_t a01 = sladdr(pr0, o + 16), a11 = sladdr(pr1, o + 16);
                ah[mt][0] = *(const uint32_t*)(Ab + a00);
                ah[mt][1] = *(const uint32_t*)(Ab + a10);
                ah[mt][2] = *(const uint32_t*)(Ab + a01);
                ah[mt][3] = *(const uint32_t*)(Ab + a11);
                al[mt][0] = *(const uint32_t*)(Ab + APL + a00);
                al[mt][1] = *(const uint32_t*)(Ab + APL + a10);
                al[mt][2] = *(const uint32_t*)(Ab + APL + a01);
                al[mt][3] = *(const uint32_t*)(Ab + APL + a11);
            }
            uint32_t bf[4][2];
#pragma unroll
            for (int j = 0; j < 4; j++) {
                int prB = (tb << 5) + (j << 3) + lr;
                bf[j][0] = *(const uint32_t*)(Bb + sladdr(prB, o));
                bf[j][1] = *(const uint32_t*)(Bb + sladdr(prB, o + 16));
            }
#pragma unroll
            for (int mt = 0; mt < 2; mt++)
#pragma unroll
                for (int j = 0; j < 4; j++) {
                    mma_fp16(acc[mt][j], ah[mt], bf[j]);
                    mma_fp16(acc[mt][j], al[mt], bf[j]);
                }
        }
    };

    stage_copy(0, 0);
    CP_COMMIT();

#pragma unroll 1
    for (int s = 0; s < NS; s++) {
        __syncthreads();                 // compute(s-1) done -> buffer (s+1)&1 free
        if (s + 1 < NS) stage_copy(s + 1, (s + 1) & 1);
        CP_COMMIT();
        CP_WAIT1();                      // stage s deposits landed (this thread)
        __syncthreads();                 // all deposits visible

        const char* Ab = smem + (s & 1) * BUF;
        const char* Bb = Ab + AB;

        if (CONV == 2 && s >= 9) {
            bundle(Ab, Bb, 1, 1, 0);
        } else {
#pragma unroll
            for (int kh = 0; kh < 3; kh++)
#pragma unroll
                for (int kw = 0; kw < 3; kw++)
                    bundle(Ab, Bb, kh, kw, kh * 3 + kw);
        }
    }

    // ---- epilogue ----
    float bb0[4], bb1[4];
#pragma unroll
    for (int j = 0; j < 4; j++) {
        int co = 8 * j + 2 * lc;
        bb0[j] = bias0[co]     + ((CONV == 2) ? bias1[co]     : 0.f);
        bb1[j] = bias0[co + 1] + ((CONV == 2) ? bias1[co + 1] : 0.f);
    }

#pragma unroll
    for (int mt = 0; mt < 2; mt++) {
        int h = 2 * wid + mt;
#pragma unroll
        for (int rr = 0; rr < 2; rr++) {
            int w = lr + 8 * rr;
            if (CONV == 1) {
                size_t ridx = bOff + (size_t)(t + 1) * C18 + (d + 1) * S18 + (h + 1) * 18 + (w + 1);
                uint32_t* oh = (uint32_t*)(outHi + ridx * 32);
                uint32_t* ol = (uint32_t*)(outLo + ridx * 32);
#pragma unroll
                for (int j = 0; j < 4; j++) {
                    float v0 = fmaxf(acc[mt][j][rr * 2 + 0] + bb0[j], 0.f);
                    float v1 = fmaxf(acc[mt][j][rr * 2 + 1] + bb1[j], 0.f);
                    __half h0, l0, h1, l1;
                    hsplit(v0, h0, l0);
                    hsplit(v1, h1, l1);
                    oh[4 * j + lc] = pack_hf(h0, h1);
                    ol[4 * j + lc] = pack_hf(l0, l1);
                }
            } else {
                size_t obase = ((size_t)b * 32) << 16;
                int opos = (t << 12) + (d << 8) + (h << 4) + w;
#pragma unroll
                for (int j = 0; j < 4; j++) {
                    int co = 8 * j + 2 * lc;
                    float v0 = fmaxf(acc[mt][j][rr * 2 + 0] + bb0[j], 0.f);
                    float v1 = fmaxf(acc[mt][j][rr * 2 + 1] + bb1[j], 0.f);
                    outF[obase + (((size_t)co) << 16) + opos]       = v0;
                    outF[obase + (((size_t)(co + 1)) << 16) + opos] = v1;
                }
            }
        }
    }
}

// ---------------------------------------------------------------------------
extern "C" void kernel_launch(void* const* d_in, const int* in_sizes, int n_in,
                              void* d_out, int out_size)
{
    const float* x1   = (const float*)d_in[0];
    const float* x2   = (const float*)d_in[1];
    const float* up_w = (const float*)d_in[2];
    const float* up_b = (const float*)d_in[3];
    const float* w1   = (const float*)d_in[4];
    const float* b1   = (const float*)d_in[5];
    const float* w2   = (const float*)d_in[6];
    const float* b2   = (const float*)d_in[7];
    const float* w3   = (const float*)d_in[8];
    const float* b3   = (const float*)d_in[9];
    float* out = (float*)d_out;

    __half *xcH, *xcL, *y1H, *y1L, *w1F, *w2F, *w3F;
    cudaGetSymbolAddress((void**)&xcH, g_xcH);
    cudaGetSymbolAddress((void**)&xcL, g_xcL);
    cudaGetSymbolAddress((void**)&y1H, g_y1H);
    cudaGetSymbolAddress((void**)&y1L, g_y1L);
    cudaGetSymbolAddress((void**)&w1F, g_w1F);
    cudaGetSymbolAddress((void**)&w2F, g_w2F);
    cudaGetSymbolAddress((void**)&w3F, g_w3F);

    constexpr int SMB = 2 * (2 * 324 * 64 + 9 * 32 * 64);  // 119808 bytes
    cudaFuncSetAttribute(conv_mma<1>, cudaFuncAttributeMaxDynamicSharedMemorySize, SMB);
    cudaFuncSetAttribute(conv_mma<2>, cudaFuncAttributeMaxDynamicSharedMemorySize, SMB);

    pack_kernel<<<512, 256>>>(x1, x2, up_w, up_b);
    wprep_kernel<<<512, 256>>>(w1, w2, w3);

    // conv1: y1 = relu(conv(xc, w1) + b1)
    conv_mma<1><<<dim3(256, 2), 256, SMB>>>(
        xcH, xcL, w1F, nullptr, nullptr, nullptr,
        b1, nullptr, y1H, y1L, nullptr);

    // conv2: out = relu(conv(y1, w2) + b2 + conv1x1(xc, w3) + b3)
    conv_mma<2><<<dim3(256, 2), 256, SMB>>>(
        y1H, y1L, w2F, xcH, xcL, w3F,
        b2, b3, nullptr, nullptr, out);
}

// round 13
// speedup vs baseline: 5.7696x; 1.7566x over previous
#include <cuda_runtime.h>
#include <cuda_fp16.h>
#include <cstdint>

// Shapes (fixed):
//  x1  [2,64,8,8,8,8]   x2 [2,32,16,16,16,16]
//  up_w[64,32,2,2,2,2]  up_b[32]
//  w1  [32,64,3,3,3,3]  b1[32]
//  w2  [32,32,3,3,3,3]  b2[32]
//  w3  [32,64]          b3[32]
//  out [2,32,16,16,16,16] fp32
//
// Implicit GEMM, mma.sync.m16n8k16 fp16, SINGLE pass (activations and
// weights rounded to fp16 once; fp32 accumulate). CTA = full (b,t,d) plane
// (M=256), 8 warps x m32. Stage = (kt,kd) [x ci-half for conv1]; kh,kw are
// address shifts into one staged 18x18 channel-sliced plane.
// Smem rows are 64B slots packed 2-per-128B-line with a line-rotation swizzle.

#define F18 104976   // 18^4
#define C18 5832     // 18^3
#define S18 324      // 18^2

// ---- scratch (device globals; zero-initialized at module load — halos are
// never written, interiors are fully rewritten every call) ----
__device__ __half g_xcF[2 * F18 * 64];
__device__ __half g_y1F[2 * F18 * 32];
__device__ __half g_w1F[81 * 32 * 64];
__device__ __half g_w2F[81 * 32 * 32];
__device__ __half g_w3F[2 * 32 * 32];

// ---- helpers ----
__device__ __forceinline__ uint32_t smem_u32(const void* p) {
    return (uint32_t)__cvta_generic_to_shared(p);
}
__device__ __forceinline__ void cp16(uint32_t dst, const void* src) {
    asm volatile("cp.async.cg.shared.global [%0], [%1], 16;" :: "r"(dst), "l"(src) : "memory");
}
#define CP_COMMIT() asm volatile("cp.async.commit_group;" ::: "memory")
#define CP_WAIT1()  asm volatile("cp.async.wait_group 1;"  ::: "memory")

__device__ __forceinline__ void mma_fp16(float* d, const uint32_t* a, const uint32_t* b) {
    asm volatile(
        "mma.sync.aligned.m16n8k16.row.col.f32.f16.f16.f32 "
        "{%0,%1,%2,%3}, {%4,%5,%6,%7}, {%8,%9}, {%0,%1,%2,%3};"
        : "+f"(d[0]), "+f"(d[1]), "+f"(d[2]), "+f"(d[3])
        : "r"(a[0]), "r"(a[1]), "r"(a[2]), "r"(a[3]), "r"(b[0]), "r"(b[1]));
}
__device__ __forceinline__ uint32_t pack_hf(__half a, __half b) {
    return (uint32_t)__half_as_ushort(a) | ((uint32_t)__half_as_ushort(b) << 16);
}
// Packed-64B-slot smem offset: row pr (64B of data), byte o within slot (0..63)
__device__ __forceinline__ uint32_t sladdr(int pr, int o) {
    return (uint32_t)(((pr >> 1) << 7) + ((pr & 1) << 6) + ((o + (((pr >> 1) & 3) << 4)) & 63));
}

// ---------------------------------------------------------------------------
// Prep kernels
// ---------------------------------------------------------------------------
// upsample x1 + concat with x2 -> padded channels-last xc (fp16)
__global__ __launch_bounds__(256) void pack_kernel(
    const float* __restrict__ x1, const float* __restrict__ x2,
    const float* __restrict__ uw, const float* __restrict__ ub)
{
    int bx = blockIdx.x;
    int b = bx >> 8, t = (bx >> 4) & 15, d = bx & 15;
    int tid = threadIdx.x;
    int h = tid >> 4, w = tid & 15;

    float acc[32];
#pragma unroll
    for (int co = 0; co < 32; co++) acc[co] = ub[co];

    int sub = ((t & 1) << 3) | ((d & 1) << 2) | ((h & 1) << 1) | (w & 1);
    const float* xp = x1 + (((size_t)b * 64) << 12) + ((t >> 1) << 9) + ((d >> 1) << 6) + ((h >> 1) << 3) + (w >> 1);
#pragma unroll 4
    for (int ci = 0; ci < 64; ci++) {
        float xv = xp[(size_t)ci << 12];
        const float* wr = uw + ((size_t)ci << 9) + sub;
#pragma unroll
        for (int co = 0; co < 32; co++) acc[co] += xv * wr[co << 4];
    }

    size_t ridx = (size_t)b * F18 + (size_t)(t + 1) * C18 + (d + 1) * S18 + (h + 1) * 18 + (w + 1);
    __half* of = g_xcF + ridx * 64;
    int pos = (t << 12) + (d << 8) + (h << 4) + w;
#pragma unroll
    for (int c = 0; c < 32; c++) {
        of[c] = __float2half_rn(x2[(((size_t)(b * 32 + c)) << 16) + pos]);
    }
#pragma unroll
    for (int co = 0; co < 32; co++) {
        of[32 + co] = __float2half_rn(acc[co]);
    }
}

// weights -> [tap81][co][ci] fp16 (rounded once)
__global__ void wprep_kernel(const float* __restrict__ w1, const float* __restrict__ w2,
                             const float* __restrict__ w3)
{
    int i = blockIdx.x * blockDim.x + threadIdx.x;
    int stride = gridDim.x * blockDim.x;
    for (; i < 81 * 32 * 64 + 81 * 32 * 32 + 2 * 32 * 32; i += stride) {
        if (i < 81 * 32 * 64) {
            int tp = i >> 11, rem = i & 2047;
            int co = rem >> 6, ci = rem & 63;
            g_w1F[i] = __float2half_rn(w1[((size_t)(co * 64 + ci)) * 81 + tp]);
        } else if (i < 81 * 32 * 64 + 81 * 32 * 32) {
            int j = i - 81 * 32 * 64;
            int tp = j >> 10, rem = j & 1023;
            int co = rem >> 5, ci = rem & 31;
            g_w2F[j] = __float2half_rn(w2[((size_t)(co * 32 + ci)) * 81 + tp]);
        } else {
            int k = i - 81 * 32 * 64 - 81 * 32 * 32;
            int half_ = k >> 10, rem = k & 1023;
            int co = rem >> 5, ci = rem & 31;
            g_w3F[k] = __float2half_rn(w3[co * 64 + half_ * 32 + ci]);
        }
    }
}

// ---------------------------------------------------------------------------
// Conv kernel. M=256 (full plane per (b,t,d)), 8 warps x m32, N=32, KC=32.
//  CONV=1: stages = (kt,kd)x(ci-half) = 18; A = xc 32-ch slice; B = w1 slice.
//  CONV=2: stages = (kt,kd) = 9 over y1 + 2 skip stages (xc halves * w3).
// A plane per stage: 324 rows (18h' x 18w') x 32ch fp16. B: 9 taps x 32 co.
// ---------------------------------------------------------------------------
template <int CONV>
__global__ __launch_bounds__(256) void conv_mma(
    const __half* __restrict__ aF,
    const __half* __restrict__ wF,
    const __half* __restrict__ sF,
    const __half* __restrict__ w3F,
    const float* __restrict__ bias0, const float* __restrict__ bias1,
    __half* __restrict__ outH,
    float* __restrict__ outF)
{
    constexpr int NS   = (CONV == 1) ? 18 : 11;
    constexpr int APL  = 324 * 64;            // 20736 B A plane
    constexpr int BB   = 9 * 32 * 64;         // 18432
    constexpr int BUF  = APL + BB;            // 39168
    constexpr int ACH  = 324 * 4;             // A 16B chunks
    constexpr int CHT  = ACH + 9 * 32 * 4;    // 2448 chunk slots
    constexpr int WROW = (CONV == 1) ? 64 : 32;  // co stride in source weights
    constexpr int TAPS = 32 * WROW;

    extern __shared__ __align__(128) char smem[];
    uint32_t sb0 = smem_u32(smem);

    int bx  = blockIdx.x;
    int t   = bx >> 4, d = bx & 15;
    int b   = blockIdx.y;
    int tid = threadIdx.x;
    int wid = tid >> 5;
    int lane = tid & 31;
    int lr = lane >> 2, lc = lane & 3;
    size_t bOff = (size_t)b * F18;

    float acc[2][4][4];
#pragma unroll
    for (int mt = 0; mt < 2; mt++)
#pragma unroll
        for (int j = 0; j < 4; j++)
#pragma unroll
            for (int e = 0; e < 4; e++) acc[mt][j][e] = 0.f;

    // ---- stage copy ----
    auto stage_copy = [&](int s, int bufi) {
        int kt, kd, chbase, srcch, ntap;
        const __half *src_, *wsrc;
        if (CONV == 2 && s >= 9) {
            int half_ = s - 9;
            kt = 1; kd = 1;
            src_ = sF; srcch = 64; chbase = half_ << 5;
            wsrc = w3F + (half_ << 10);
            ntap = 1;
        } else {
            int pair  = (CONV == 1) ? (s >> 1) : s;
            int half_ = (CONV == 1) ? (s & 1) : 0;
            kt = pair / 3; kd = pair % 3;
            src_ = aF;
            srcch = (CONV == 1) ? 64 : 32;
            chbase = half_ << 5;
            wsrc = wF + (size_t)(kt * 27 + kd * 9) * TAPS + chbase;
            ntap = 9;
        }
        uint32_t sb = sb0 + (uint32_t)bufi * BUF;
        size_t abase = bOff + (size_t)(t + kt) * C18 + (size_t)(d + kd) * S18;
#pragma unroll
        for (int ii = 0; ii < 10; ii++) {
            int i = tid + ii * 256;
            if (i < ACH) {
                int pr = i >> 2, c = i & 3;
                const __half* g = src_ + (abase + pr) * srcch + chbase + c * 8;
                cp16(sb + sladdr(pr, c << 4), g);
            } else if (i < CHT) {
                int j2 = i - ACH;
                int tt = j2 >> 7;
                int e  = j2 & 127;
                int r  = e >> 2, c = e & 3;
                if (tt < ntap) {
                    const __half* g = wsrc + (size_t)tt * TAPS + r * WROW + c * 8;
                    cp16(sb + APL + sladdr((tt << 5) + r, c << 4), g);
                }
            }
        }
    };

    // ---- compute bundle: one (kh,kw) tap, both ks, both mt, all N ----
    auto bundle = [&](const char* Ab, const char* Bb, int kh, int kw, int tb) {
#pragma unroll
        for (int ks = 0; ks < 2; ks++) {
            int o = (ks << 5) + (lc << 2);
            uint32_t af[2][4];
#pragma unroll
            for (int mt = 0; mt < 2; mt++) {
                int pr0 = (2 * wid + mt + kh) * 18 + lr + kw;
                int pr1 = pr0 + 8;
                af[mt][0] = *(const uint32_t*)(Ab + sladdr(pr0, o));
                af[mt][1] = *(const uint32_t*)(Ab + sladdr(pr1, o));
                af[mt][2] = *(const uint32_t*)(Ab + sladdr(pr0, o + 16));
                af[mt][3] = *(const uint32_t*)(Ab + sladdr(pr1, o + 16));
            }
            uint32_t bf[4][2];
#pragma unroll
            for (int j = 0; j < 4; j++) {
                int prB = (tb << 5) + (j << 3) + lr;
                bf[j][0] = *(const uint32_t*)(Bb + sladdr(prB, o));
                bf[j][1] = *(const uint32_t*)(Bb + sladdr(prB, o + 16));
            }
#pragma unroll
            for (int mt = 0; mt < 2; mt++)
#pragma unroll
                for (int j = 0; j < 4; j++)
                    mma_fp16(acc[mt][j], af[mt], bf[j]);   // 8 independent chains
        }
    };

    stage_copy(0, 0);
    CP_COMMIT();

#pragma unroll 1
    for (int s = 0; s < NS; s++) {
        __syncthreads();                 // compute(s-1) done -> buffer (s+1)&1 free
        if (s + 1 < NS) stage_copy(s + 1, (s + 1) & 1);
        CP_COMMIT();
        CP_WAIT1();                      // stage s deposits landed (this thread)
        __syncthreads();                 // all deposits visible

        const char* Ab = smem + (s & 1) * BUF;
        const char* Bb = Ab + APL;

        if (CONV == 2 && s >= 9) {
            bundle(Ab, Bb, 1, 1, 0);
        } else {
#pragma unroll
            for (int kh = 0; kh < 3; kh++)
#pragma unroll
                for (int kw = 0; kw < 3; kw++)
                    bundle(Ab, Bb, kh, kw, kh * 3 + kw);
        }
    }

    // ---- epilogue ----
    float bb0[4], bb1[4];
#pragma unroll
    for (int j = 0; j < 4; j++) {
        int co = 8 * j + 2 * lc;
        bb0[j] = bias0[co]     + ((CONV == 2) ? bias1[co]     : 0.f);
        bb1[j] = bias0[co + 1] + ((CONV == 2) ? bias1[co + 1] : 0.f);
    }

#pragma unroll
    for (int mt = 0; mt < 2; mt++) {
        int h = 2 * wid + mt;
#pragma unroll
        for (int rr = 0; rr < 2; rr++) {
            int w = lr + 8 * rr;
            if (CONV == 1) {
                size_t ridx = bOff + (size_t)(t + 1) * C18 + (d + 1) * S18 + (h + 1) * 18 + (w + 1);
                uint32_t* oh = (uint32_t*)(outH + ridx * 32);
#pragma unroll
                for (int j = 0; j < 4; j++) {
                    float v0 = fmaxf(acc[mt][j][rr * 2 + 0] + bb0[j], 0.f);
                    float v1 = fmaxf(acc[mt][j][rr * 2 + 1] + bb1[j], 0.f);
                    oh[4 * j + lc] = pack_hf(__float2half_rn(v0), __float2half_rn(v1));
                }
            } else {
                size_t obase = ((size_t)b * 32) << 16;
                int opos = (t << 12) + (d << 8) + (h << 4) + w;
#pragma unroll
                for (int j = 0; j < 4; j++) {
                    int co = 8 * j + 2 * lc;
                    float v0 = fmaxf(acc[mt][j][rr * 2 + 0] + bb0[j], 0.f);
                    float v1 = fmaxf(acc[mt][j][rr * 2 + 1] + bb1[j], 0.f);
                    outF[obase + (((size_t)co) << 16) + opos]       = v0;
                    outF[obase + (((size_t)(co + 1)) << 16) + opos] = v1;
                }
            }
        }
    }
}

// ---------------------------------------------------------------------------
extern "C" void kernel_launch(void* const* d_in, const int* in_sizes, int n_in,
                              void* d_out, int out_size)
{
    const float* x1   = (const float*)d_in[0];
    const float* x2   = (const float*)d_in[1];
    const float* up_w = (const float*)d_in[2];
    const float* up_b = (const float*)d_in[3];
    const float* w1   = (const float*)d_in[4];
    const float* b1   = (const float*)d_in[5];
    const float* w2   = (const float*)d_in[6];
    const float* b2   = (const float*)d_in[7];
    const float* w3   = (const float*)d_in[8];
    const float* b3   = (const float*)d_in[9];
    float* out = (float*)d_out;

    __half *xcF, *y1F, *w1F, *w2F, *w3F;
    cudaGetSymbolAddress((void**)&xcF, g_xcF);
    cudaGetSymbolAddress((void**)&y1F, g_y1F);
    cudaGetSymbolAddress((void**)&w1F, g_w1F);
    cudaGetSymbolAddress((void**)&w2F, g_w2F);
    cudaGetSymbolAddress((void**)&w3F, g_w3F);

    constexpr int SMB = 2 * (324 * 64 + 9 * 32 * 64);  // 78336 bytes
    cudaFuncSetAttribute(conv_mma<1>, cudaFuncAttributeMaxDynamicSharedMemorySize, SMB);
    cudaFuncSetAttribute(conv_mma<2>, cudaFuncAttributeMaxDynamicSharedMemorySize, SMB);

    pack_kernel<<<512, 256>>>(x1, x2, up_w, up_b);
    wprep_kernel<<<512, 256>>>(w1, w2, w3);

    // conv1: y1 = relu(conv(xc, w1) + b1)
    conv_mma<1><<<dim3(256, 2), 256, SMB>>>(
        xcF, w1F, nullptr, nullptr,
        b1, nullptr, y1F, nullptr);

    // conv2: out = relu(conv(y1, w2) + b2 + conv1x1(xc, w3) + b3)
    conv_mma<2><<<dim3(256, 2), 256, SMB>>>(
        y1F, w2F, xcF, w3F,
        b2, b3, nullptr, out);
}

// round 14
// speedup vs baseline: 7.0800x; 1.2271x over previous
#include <cuda_runtime.h>
#include <cuda_fp16.h>
#include <cstdint>

// Shapes (fixed):
//  x1  [2,64,8,8,8,8]   x2 [2,32,16,16,16,16]
//  up_w[64,32,2,2,2,2]  up_b[32]
//  w1  [32,64,3,3,3,3]  b1[32]
//  w2  [32,32,3,3,3,3]  b2[32]
//  w3  [32,64]          b3[32]
//  out [2,32,16,16,16,16] fp32
//
// Implicit GEMM, mma.sync.m16n8k16 fp16 single-pass (fp32 accum).
// CTA = full (b,t,d) plane (M=256), 128 threads, 4 warps x m64.
// Stage = (kt,kd) x ci-16-slice; kh,kw are address shifts into one staged
// 18x18 channel-sliced plane. KC=16 keeps smem at 39KB -> 3 CTAs/SM.
// Smem rows are 32B slots, 4-per-128B-line, 16B parity rotation (conflict-free).

#define F18 104976   // 18^4
#define C18 5832     // 18^3
#define S18 324      // 18^2

// ---- scratch (device globals; zero-initialized at module load — halos are
// never written, interiors fully rewritten every call) ----
__device__ __half g_xcF[2 * F18 * 64];
__device__ __half g_y1F[2 * F18 * 32];
__device__ __half g_w1F[81 * 32 * 64];
__device__ __half g_w2F[81 * 32 * 32];
__device__ __half g_w3F[2 * 32 * 32];

// ---- helpers ----
__device__ __forceinline__ uint32_t smem_u32(const void* p) {
    return (uint32_t)__cvta_generic_to_shared(p);
}
__device__ __forceinline__ void cp16(uint32_t dst, const void* src) {
    asm volatile("cp.async.cg.shared.global [%0], [%1], 16;" :: "r"(dst), "l"(src) : "memory");
}
#define CP_COMMIT() asm volatile("cp.async.commit_group;" ::: "memory")
#define CP_WAIT1()  asm volatile("cp.async.wait_group 1;"  ::: "memory")

__device__ __forceinline__ void mma_fp16(float* d, const uint32_t* a, const uint32_t* b) {
    asm volatile(
        "mma.sync.aligned.m16n8k16.row.col.f32.f16.f16.f32 "
        "{%0,%1,%2,%3}, {%4,%5,%6,%7}, {%8,%9}, {%0,%1,%2,%3};"
        : "+f"(d[0]), "+f"(d[1]), "+f"(d[2]), "+f"(d[3])
        : "r"(a[0]), "r"(a[1]), "r"(a[2]), "r"(a[3]), "r"(b[0]), "r"(b[1]));
}
__device__ __forceinline__ uint32_t pack_hf(__half a, __half b) {
    return (uint32_t)__half_as_ushort(a) | ((uint32_t)__half_as_ushort(b) << 16);
}
// 32B-slot smem offset: row pr (32B of data), byte o in slot (0..31).
// 4 slots per 128B line; 16B rotation by line parity -> conflict-free frags.
__device__ __forceinline__ uint32_t sl32(int pr, int o) {
    return (uint32_t)(((pr >> 2) << 7) + ((pr & 3) << 5) + ((o + (((pr >> 2) & 1) << 4)) & 31));
}

// ---------------------------------------------------------------------------
// Prep kernels
// ---------------------------------------------------------------------------
// upsample x1 + concat with x2 -> padded channels-last xc (fp16)
__global__ __launch_bounds__(256) void pack_kernel(
    const float* __restrict__ x1, const float* __restrict__ x2,
    const float* __restrict__ uw, const float* __restrict__ ub)
{
    int bx = blockIdx.x;
    int b = bx >> 8, t = (bx >> 4) & 15, d = bx & 15;
    int tid = threadIdx.x;
    int h = tid >> 4, w = tid & 15;

    float acc[32];
#pragma unroll
    for (int co = 0; co < 32; co++) acc[co] = ub[co];

    int sub = ((t & 1) << 3) | ((d & 1) << 2) | ((h & 1) << 1) | (w & 1);
    const float* xp = x1 + (((size_t)b * 64) << 12) + ((t >> 1) << 9) + ((d >> 1) << 6) + ((h >> 1) << 3) + (w >> 1);
#pragma unroll 4
    for (int ci = 0; ci < 64; ci++) {
        float xv = xp[(size_t)ci << 12];
        const float* wr = uw + ((size_t)ci << 9) + sub;
#pragma unroll
        for (int co = 0; co < 32; co++) acc[co] += xv * wr[co << 4];
    }

    size_t ridx = (size_t)b * F18 + (size_t)(t + 1) * C18 + (d + 1) * S18 + (h + 1) * 18 + (w + 1);
    uint32_t row[32];
    int pos = (t << 12) + (d << 8) + (h << 4) + w;
#pragma unroll
    for (int c = 0; c < 16; c++) {
        float v0 = x2[(((size_t)(b * 32 + 2 * c)) << 16) + pos];
        float v1 = x2[(((size_t)(b * 32 + 2 * c + 1)) << 16) + pos];
        row[c] = pack_hf(__float2half_rn(v0), __float2half_rn(v1));
    }
#pragma unroll
    for (int c = 0; c < 16; c++) {
        row[16 + c] = pack_hf(__float2half_rn(acc[2 * c]), __float2half_rn(acc[2 * c + 1]));
    }
    uint4* of = (uint4*)(g_xcF + ridx * 64);
#pragma unroll
    for (int q = 0; q < 8; q++)
        of[q] = make_uint4(row[4 * q], row[4 * q + 1], row[4 * q + 2], row[4 * q + 3]);
}

// weights -> [tap81][co][ci] fp16 (rounded once)
__global__ void wprep_kernel(const float* __restrict__ w1, const float* __restrict__ w2,
                             const float* __restrict__ w3)
{
    int i = blockIdx.x * blockDim.x + threadIdx.x;
    int stride = gridDim.x * blockDim.x;
    for (; i < 81 * 32 * 64 + 81 * 32 * 32 + 2 * 32 * 32; i += stride) {
        if (i < 81 * 32 * 64) {
            int tp = i >> 11, rem = i & 2047;
            int co = rem >> 6, ci = rem & 63;
            g_w1F[i] = __float2half_rn(w1[((size_t)(co * 64 + ci)) * 81 + tp]);
        } else if (i < 81 * 32 * 64 + 81 * 32 * 32) {
            int j = i - 81 * 32 * 64;
            int tp = j >> 10, rem = j & 1023;
            int co = rem >> 5, ci = rem & 31;
            g_w2F[j] = __float2half_rn(w2[((size_t)(co * 32 + ci)) * 81 + tp]);
        } else {
            int k = i - 81 * 32 * 64 - 81 * 32 * 32;
            int half_ = k >> 10, rem = k & 1023;
            int co = rem >> 5, ci = rem & 31;
            g_w3F[k] = __float2half_rn(w3[co * 64 + half_ * 32 + ci]);
        }
    }
}

// ---------------------------------------------------------------------------
// Conv kernel. M=256 plane per (b,t,d), 4 warps x m64, N=32, KC=16/stage.
//  CONV=1: stages = (kt,kd) x ci-quarter = 36; A = xc 16-ch slice; B = w1 slice.
//  CONV=2: stages = (kt,kd) x ci-half = 18 over y1 + 4 skip stages (xc quarters * w3).
// A plane/stage: 324 rows x 16ch fp16 (32B rows). B: 9 taps x 32 co x 32B.
// ---------------------------------------------------------------------------
template <int CONV>
__global__ __launch_bounds__(128, 3) void conv_mma(
    const __half* __restrict__ aF,
    const __half* __restrict__ wF,
    const __half* __restrict__ sF,
    const __half* __restrict__ w3F,
    const float* __restrict__ bias0, const float* __restrict__ bias1,
    __half* __restrict__ outH,
    float* __restrict__ outF)
{
    constexpr int NS   = (CONV == 1) ? 36 : 22;
    constexpr int NMAIN= (CONV == 1) ? 36 : 18;
    constexpr int APL  = 324 * 32;            // 10368 B A plane
    constexpr int BB   = 9 * 32 * 32;         // 9216 B
    constexpr int BUF  = APL + BB;            // 19584
    constexpr int ACH  = 324 * 2;             // A 16B chunks = 648
    constexpr int CHT  = ACH + 9 * 32 * 2;    // 1224 chunk slots
    constexpr int WROW = (CONV == 1) ? 64 : 32;  // ci stride per co row in gmem
    constexpr int TAPS = 32 * WROW;
    constexpr int QSH  = (CONV == 1) ? 2 : 1;    // log2(slices per (kt,kd))
    constexpr int QMSK = (CONV == 1) ? 3 : 1;

    extern __shared__ __align__(128) char smem[];
    uint32_t sb0 = smem_u32(smem);

    int bx  = blockIdx.x;
    int t   = bx >> 4, d = bx & 15;
    int b   = blockIdx.y;
    int tid = threadIdx.x;
    int wid = tid >> 5;
    int lane = tid & 31;
    int lr = lane >> 2, lc = lane & 3;
    size_t bOff = (size_t)b * F18;

    float acc[4][4][4];
#pragma unroll
    for (int mt = 0; mt < 4; mt++)
#pragma unroll
        for (int j = 0; j < 4; j++)
#pragma unroll
            for (int e = 0; e < 4; e++) acc[mt][j][e] = 0.f;

    // ---- stage copy (all 128 threads) ----
    auto stage_copy = [&](int s, int bufi) {
        int kt, kd, chbase, srcch, ntap;
        const __half *src_, *wsrc;
        if (CONV == 2 && s >= 18) {
            int q = s - 18;                    // xc quarter 0..3
            kt = 1; kd = 1;
            src_ = sF; srcch = 64; chbase = q << 4;
            wsrc = w3F + ((q >> 1) << 10) + ((q & 1) << 4);
            ntap = 1;
        } else {
            int pair = s >> QSH;
            int q    = s & QMSK;
            kt = pair / 3; kd = pair % 3;
            src_ = aF;
            srcch = (CONV == 1) ? 64 : 32;
            chbase = q << 4;
            wsrc = wF + (size_t)(kt * 27 + kd * 9) * TAPS + chbase;
            ntap = 9;
        }
        uint32_t sb = sb0 + (uint32_t)bufi * BUF;
        size_t abase = bOff + (size_t)(t + kt) * C18 + (size_t)(d + kd) * S18;
#pragma unroll
        for (int ii = 0; ii < 10; ii++) {
            int i = tid + ii * 128;
            if (i < ACH) {
                int pr = i >> 1, c = i & 1;
                const __half* g = src_ + (abase + pr) * srcch + chbase + c * 8;
                cp16(sb + sl32(pr, c << 4), g);
            } else if (i < CHT) {
                int j2 = i - ACH;
                int tt = j2 >> 6;
                int e  = j2 & 63;
                int r  = e >> 1, c = e & 1;
                if (tt < ntap) {
                    const __half* g = wsrc + (size_t)tt * TAPS + r * WROW + c * 8;
                    cp16(sb + APL + sl32((tt << 5) + r, c << 4), g);
                }
            }
        }
    };

    // ---- compute bundle: one (kh,kw) tap, 4 mt x 4 j, single k16 ----
    auto bundle = [&](const char* Ab, const char* Bb, int kh, int kw, int tb) {
        int o = lc << 2;
        uint32_t af[4][4];
#pragma unroll
        for (int mt = 0; mt < 4; mt++) {
            int pr0 = (4 * wid + mt + kh) * 18 + lr + kw;
            int pr1 = pr0 + 8;
            af[mt][0] = *(const uint32_t*)(Ab + sl32(pr0, o));
            af[mt][1] = *(const uint32_t*)(Ab + sl32(pr1, o));
            af[mt][2] = *(const uint32_t*)(Ab + sl32(pr0, o + 16));
            af[mt][3] = *(const uint32_t*)(Ab + sl32(pr1, o + 16));
        }
        uint32_t bf[4][2];
#pragma unroll
        for (int j = 0; j < 4; j++) {
            int prB = (tb << 5) + (j << 3) + lr;
            bf[j][0] = *(const uint32_t*)(Bb + sl32(prB, o));
            bf[j][1] = *(const uint32_t*)(Bb + sl32(prB, o + 16));
        }
#pragma unroll
        for (int mt = 0; mt < 4; mt++)
#pragma unroll
            for (int j = 0; j < 4; j++)
                mma_fp16(acc[mt][j], af[mt], bf[j]);   // 16 independent chains
    };

    stage_copy(0, 0);
    CP_COMMIT();

#pragma unroll 1
    for (int s = 0; s < NS; s++) {
        __syncthreads();                 // compute(s-1) done -> buffer (s+1)&1 free
        if (s + 1 < NS) stage_copy(s + 1, (s + 1) & 1);
        CP_COMMIT();
        CP_WAIT1();                      // stage s deposits landed (this thread)
        __syncthreads();                 // all deposits visible

        const char* Ab = smem + (s & 1) * BUF;
        const char* Bb = Ab + APL;

        if (CONV == 2 && s >= NMAIN) {
            bundle(Ab, Bb, 1, 1, 0);
        } else {
#pragma unroll
            for (int kh = 0; kh < 3; kh++)
#pragma unroll
                for (int kw = 0; kw < 3; kw++)
                    bundle(Ab, Bb, kh, kw, kh * 3 + kw);
        }
    }

    // ---- epilogue ----
    float bb0[4], bb1[4];
#pragma unroll
    for (int j = 0; j < 4; j++) {
        int co = 8 * j + 2 * lc;
        bb0[j] = bias0[co]     + ((CONV == 2) ? bias1[co]     : 0.f);
        bb1[j] = bias0[co + 1] + ((CONV == 2) ? bias1[co + 1] : 0.f);
    }

#pragma unroll
    for (int mt = 0; mt < 4; mt++) {
        int h = 4 * wid + mt;
#pragma unroll
        for (int rr = 0; rr < 2; rr++) {
            int w = lr + 8 * rr;
            if (CONV == 1) {
                size_t ridx = bOff + (size_t)(t + 1) * C18 + (d + 1) * S18 + (h + 1) * 18 + (w + 1);
                uint32_t* oh = (uint32_t*)(outH + ridx * 32);
#pragma unroll
                for (int j = 0; j < 4; j++) {
                    float v0 = fmaxf(acc[mt][j][rr * 2 + 0] + bb0[j], 0.f);
                    float v1 = fmaxf(acc[mt][j][rr * 2 + 1] + bb1[j], 0.f);
                    oh[4 * j + lc] = pack_hf(__float2half_rn(v0), __float2half_rn(v1));
                }
            } else {
                size_t obase = ((size_t)b * 32) << 16;
                int opos = (t << 12) + (d << 8) + (h << 4) + w;
#pragma unroll
                for (int j = 0; j < 4; j++) {
                    int co = 8 * j + 2 * lc;
                    float v0 = fmaxf(acc[mt][j][rr * 2 + 0] + bb0[j], 0.f);
                    float v1 = fmaxf(acc[mt][j][rr * 2 + 1] + bb1[j], 0.f);
                    outF[obase + (((size_t)co) << 16) + opos]       = v0;
                    outF[obase + (((size_t)(co + 1)) << 16) + opos] = v1;
                }
            }
        }
    }
}

// ---------------------------------------------------------------------------
extern "C" void kernel_launch(void* const* d_in, const int* in_sizes, int n_in,
                              void* d_out, int out_size)
{
    const float* x1   = (const float*)d_in[0];
    const float* x2   = (const float*)d_in[1];
    const float* up_w = (const float*)d_in[2];
    const float* up_b = (const float*)d_in[3];
    const float* w1   = (const float*)d_in[4];
    const float* b1   = (const float*)d_in[5];
    const float* w2   = (const float*)d_in[6];
    const float* b2   = (const float*)d_in[7];
    const float* w3   = (const float*)d_in[8];
    const float* b3   = (const float*)d_in[9];
    float* out = (float*)d_out;

    __half *xcF, *y1F, *w1F, *w2F, *w3F;
    cudaGetSymbolAddress((void**)&xcF, g_xcF);
    cudaGetSymbolAddress((void**)&y1F, g_y1F);
    cudaGetSymbolAddress((void**)&w1F, g_w1F);
    cudaGetSymbolAddress((void**)&w2F, g_w2F);
    cudaGetSymbolAddress((void**)&w3F, g_w3F);

    constexpr int SMB = 2 * (324 * 32 + 9 * 32 * 32);  // 39168 bytes
    cudaFuncSetAttribute(conv_mma<1>, cudaFuncAttributeMaxDynamicSharedMemorySize, SMB);
    cudaFuncSetAttribute(conv_mma<2>, cudaFuncAttributeMaxDynamicSharedMemorySize, SMB);

    pack_kernel<<<512, 256>>>(x1, x2, up_w, up_b);
    wprep_kernel<<<512, 256>>>(w1, w2, w3);

    // conv1: y1 = relu(conv(xc, w1) + b1)
    conv_mma<1><<<dim3(256, 2), 128, SMB>>>(
        xcF, w1F, nullptr, nullptr,
        b1, nullptr, y1F, nullptr);

    // conv2: out = relu(conv(y1, w2) + b2 + conv1x1(xc, w3) + b3)
    conv_mma<2><<<dim3(256, 2), 128, SMB>>>(
        y1F, w2F, xcF, w3F,
        b2, b3, nullptr, out);
}